// round 15
// baseline (speedup 1.0000x reference)
#include <cuda_runtime.h>
#include <cuda_bf16.h>
#include <math.h>
#include <stdint.h>

#define Bb 8
#define Rr 1024
#define Dm 256
#define Hh 8
#define Ll 2
#define Ee 32768
#define FFd 1024
#define HDd 32
#define NEG -1000000000.0f

#define Mrows (Bb * Rr) // 8192
#define QSCALE 0.17677669529663687f

// ---------------- scratch (device globals; no allocation allowed) -----------
__device__ float g_mask[(size_t)Bb * Rr * Rr];          // 32 MB (fp32 build)
__device__ __nv_bfloat16 g_maskh[(size_t)Bb * Rr * Rr]; // 16 MB (attention copy)
__device__ float g_tmp [(size_t)Mrows * Dm];            // 8 MB
__device__ __nv_bfloat16 g_qkvh[(size_t)Mrows * 3 * Dm];
__device__ __nv_bfloat16 g_qkvl[(size_t)Mrows * 3 * Dm];
__device__ __nv_bfloat16 g_xh[(size_t)Mrows * Dm];
__device__ __nv_bfloat16 g_xl[(size_t)Mrows * Dm];
__device__ __nv_bfloat16 g_ah[(size_t)Mrows * Dm];
__device__ __nv_bfloat16 g_al[(size_t)Mrows * Dm];
__device__ __nv_bfloat16 g_hh[(size_t)Mrows * FFd];
__device__ __nv_bfloat16 g_hl[(size_t)Mrows * FFd];
__device__ __nv_bfloat16 g_wqkvh[(size_t)Ll * 3 * Dm * Dm];
__device__ __nv_bfloat16 g_wqkvl[(size_t)Ll * 3 * Dm * Dm];
__device__ __nv_bfloat16 g_woh[(size_t)Ll * Dm * Dm];
__device__ __nv_bfloat16 g_wol[(size_t)Ll * Dm * Dm];
__device__ __nv_bfloat16 g_w1h[(size_t)Ll * FFd * Dm];
__device__ __nv_bfloat16 g_w1l[(size_t)Ll * FFd * Dm];
__device__ __nv_bfloat16 g_w2h[(size_t)Ll * Dm * FFd];
__device__ __nv_bfloat16 g_w2l[(size_t)Ll * Dm * FFd];

// ---------------- PTX helpers (plain sm_80-class features only) --------------
__device__ __forceinline__ uint32_t smem_u32(const void* p) {
    uint32_t a;
    asm("{ .reg .u64 t; cvta.to.shared.u64 t, %1; cvt.u32.u64 %0, t; }" : "=r"(a) : "l"(p));
    return a;
}
__device__ __forceinline__ void cpasync16(uint32_t dst, const void* src) {
    asm volatile("cp.async.ca.shared.global [%0], [%1], 16;" :: "r"(dst), "l"(src) : "memory");
}
__device__ __forceinline__ void cp_commit() {
    asm volatile("cp.async.commit_group;" ::: "memory");
}
template <int N>
__device__ __forceinline__ void cp_wait() {
    asm volatile("cp.async.wait_group %0;" :: "n"(N) : "memory");
}
__device__ __forceinline__ void ldm4(uint32_t* r, uint32_t addr) {
    asm volatile("ldmatrix.sync.aligned.m8n8.x4.shared.b16 {%0,%1,%2,%3}, [%4];"
                 : "=r"(r[0]), "=r"(r[1]), "=r"(r[2]), "=r"(r[3]) : "r"(addr));
}
__device__ __forceinline__ void ldm4t(uint32_t* r, uint32_t addr) {
    asm volatile("ldmatrix.sync.aligned.m8n8.x4.trans.shared.b16 {%0,%1,%2,%3}, [%4];"
                 : "=r"(r[0]), "=r"(r[1]), "=r"(r[2]), "=r"(r[3]) : "r"(addr));
}
__device__ __forceinline__ void mma16816(float* c, const uint32_t* a, const uint32_t* b) {
    asm volatile(
        "mma.sync.aligned.m16n8k16.row.col.f32.bf16.bf16.f32 "
        "{%0,%1,%2,%3}, {%4,%5,%6,%7}, {%8,%9}, {%0,%1,%2,%3};"
        : "+f"(c[0]), "+f"(c[1]), "+f"(c[2]), "+f"(c[3])
        : "r"(a[0]), "r"(a[1]), "r"(a[2]), "r"(a[3]), "r"(b[0]), "r"(b[1]));
}
__device__ __forceinline__ uint32_t packbf(float x, float y) {
    __nv_bfloat162 t;
    t.x = __float2bfloat16(x);
    t.y = __float2bfloat16(y);
    return reinterpret_cast<uint32_t&>(t);
}

// ================= mask construction (fp32 build + direct bf16 mirror) =======
__global__ void mask_init_kernel(float* __restrict__ m, __nv_bfloat16* __restrict__ mh) {
    int i = blockIdx.x * blockDim.x + threadIdx.x;
    if (i >= Bb * Rr * Rr / 4) return;
    int rc = (i * 4) % (Rr * Rr);
    int row = rc / Rr, col = rc % Rr;
    float4 v;
    v.x = (col + 0 == row) ? 0.0f : NEG;
    v.y = (col + 1 == row) ? 0.0f : NEG;
    v.z = (col + 2 == row) ? 0.0f : NEG;
    v.w = (col + 3 == row) ? 0.0f : NEG;
    *(float4*)&m[(size_t)i * 4] = v;
    uint2 o;
    o.x = packbf(v.x, v.y);
    o.y = packbf(v.z, v.w);
    *(uint2*)&mh[(size_t)i * 4] = o;
}
__global__ void mask_edges_zero_kernel(float* __restrict__ m,
                                       __nv_bfloat16* __restrict__ mh,
                                       const int* __restrict__ ei,
                                       const int* __restrict__ keep) {
    int idx = blockIdx.x * blockDim.x + threadIdx.x;
    if (idx >= Bb * Ee) return;
    if (!keep[idx]) return;
    int b = idx / Ee, e = idx % Ee;
    int src = ei[(size_t)b * 2 * Ee + e];
    int dst = ei[(size_t)b * 2 * Ee + Ee + e];
    size_t cell = ((size_t)b * Rr + src) * Rr + dst;
    m[cell] = 0.0f;
    mh[cell] = __float2bfloat16(0.0f);
}
__global__ void mask_edges_bias_kernel(float* __restrict__ m,
                                       const int* __restrict__ ei,
                                       const int* __restrict__ rid,
                                       const int* __restrict__ keep,
                                       const float* __restrict__ rb) {
    int idx = blockIdx.x * blockDim.x + threadIdx.x;
    if (idx >= Bb * Ee) return;
    if (!keep[idx]) return;
    int b = idx / Ee, e = idx % Ee;
    int src = ei[(size_t)b * 2 * Ee + e];
    int dst = ei[(size_t)b * 2 * Ee + Ee + e];
    atomicAdd(&m[((size_t)b * Rr + src) * Rr + dst], rb[rid[idx]]);
}
__global__ void mask_edges_fix_kernel(const float* __restrict__ m,
                                      __nv_bfloat16* __restrict__ mh,
                                      const int* __restrict__ ei,
                                      const int* __restrict__ keep) {
    int idx = blockIdx.x * blockDim.x + threadIdx.x;
    if (idx >= Bb * Ee) return;
    if (!keep[idx]) return;
    int b = idx / Ee, e = idx % Ee;
    int src = ei[(size_t)b * 2 * Ee + e];
    int dst = ei[(size_t)b * 2 * Ee + Ee + e];
    size_t cell = ((size_t)b * Rr + src) * Rr + dst;
    mh[cell] = __float2bfloat16(m[cell]);
}

// ================= fp32 -> bf16 hi/lo splits ==================================
__global__ void split_kernel(const float* __restrict__ src,
                             __nv_bfloat16* __restrict__ hi,
                             __nv_bfloat16* __restrict__ lo, int n) {
    int i = blockIdx.x * blockDim.x + threadIdx.x;
    if (i >= n) return;
    float v = src[i];
    __nv_bfloat16 h = __float2bfloat16(v);
    hi[i] = h;
    lo[i] = __float2bfloat16(v - __bfloat162float(h));
}
__global__ void copy_split_kernel(const float* __restrict__ src,
                                  float* __restrict__ dst,
                                  __nv_bfloat16* __restrict__ hi,
                                  __nv_bfloat16* __restrict__ lo, int n) {
    int i = blockIdx.x * blockDim.x + threadIdx.x;
    if (i >= n) return;
    float v = src[i];
    dst[i] = v;
    __nv_bfloat16 h = __float2bfloat16(v);
    hi[i] = h;
    lo[i] = __float2bfloat16(v - __bfloat162float(h));
}
#define NWO (Ll * Dm * Dm)
#define NW1 (Ll * FFd * Dm)
#define NW2 (Ll * Dm * FFd)
__global__ void split_w3_kernel(const float* __restrict__ Wo,
                                const float* __restrict__ W1,
                                const float* __restrict__ W2,
                                __nv_bfloat16* __restrict__ woh, __nv_bfloat16* __restrict__ wol,
                                __nv_bfloat16* __restrict__ w1h, __nv_bfloat16* __restrict__ w1l,
                                __nv_bfloat16* __restrict__ w2h, __nv_bfloat16* __restrict__ w2l) {
    int i = blockIdx.x * blockDim.x + threadIdx.x;
    const float* src;
    __nv_bfloat16 *hi, *lo;
    int j;
    if (i < NWO) { src = Wo; hi = woh; lo = wol; j = i; }
    else if (i < NWO + NW1) { src = W1; hi = w1h; lo = w1l; j = i - NWO; }
    else if (i < NWO + NW1 + NW2) { src = W2; hi = w2h; lo = w2l; j = i - NWO - NW1; }
    else return;
    float v = src[j];
    __nv_bfloat16 h = __float2bfloat16(v);
    hi[j] = h;
    lo[j] = __float2bfloat16(v - __bfloat162float(h));
}

// ================= split-bf16 HMMA GEMM (64x128 tile, occ 2, persistent) ======
#define SKRB 80              // smem row stride bytes (40 bf16)
#define G_AOFF 5120          // Al offset within stage (Ah at 0)
#define G_WOFF 10240         // Wh offset within stage
#define G_STGB 30720         // stage bytes
#define GEMM_SMEM (2 * G_STGB) // 61440

__global__ void __launch_bounds__(256, 2) mma_gemm_kernel(
    const __nv_bfloat16* __restrict__ Ah, const __nv_bfloat16* __restrict__ Al,
    const __nv_bfloat16* __restrict__ Wh, const __nv_bfloat16* __restrict__ Wl,
    const float* __restrict__ bias,
    float* __restrict__ outF,
    __nv_bfloat16* __restrict__ outH, __nv_bfloat16* __restrict__ outL,
    int K, int Nld, int mode, int nTiles, int nTotal) {
    extern __shared__ __align__(16) char smem[];
    uint32_t sb = smem_u32(smem);
    const int tid = threadIdx.x, lane = tid & 31, wid = tid >> 5;
    const int wm = wid & 1, wn = wid >> 1;          // 2m x 4n warps
    const int nsteps = K >> 5;

    const int arow = lane & 15;
    const int akb = (lane >> 4) * 16;
    const int brow = ((lane >> 4) & 1) * 8 + (lane & 7);
    const int bkb = ((lane >> 3) & 1) * 16;

    for (int tile = blockIdx.x; tile < nTotal; tile += gridDim.x) {
        const int m0 = (tile / nTiles) * 64;
        const int n0 = (tile % nTiles) * 128;

        const __nv_bfloat16* base0 = Ah + (size_t)m0 * K;
        const __nv_bfloat16* base1 = Al + (size_t)m0 * K;
        const __nv_bfloat16* base2 = Wh + (size_t)n0 * K;
        const __nv_bfloat16* base3 = Wl + (size_t)n0 * K;

        float acc[2][4][4];
#pragma unroll
        for (int mt = 0; mt < 2; mt++)
#pragma unroll
            for (int nt = 0; nt < 4; nt++)
#pragma unroll
                for (int j = 0; j < 4; j++) acc[mt][nt][j] = 0.0f;

#define LOAD_STAGE(kstep, buf)                                                   \
    do {                                                                          \
        int _k0 = (kstep) * 32;                                                   \
        _Pragma("unroll")                                                         \
        for (int _i = 0; _i < 6; _i++) {                                          \
            int _task = tid + _i * 256;                                           \
            const __nv_bfloat16* _g;                                              \
            uint32_t _d;                                                          \
            if (_task < 512) {                                                    \
                int _mat = _task >> 8, _w = _task & 255;                          \
                int _row = _w >> 2, _ch = _w & 3;                                 \
                _g = (_mat ? base1 : base0) + (size_t)_row * K + _k0 + _ch * 8;   \
                _d = sb + (buf) * G_STGB + _mat * G_AOFF + _row * SKRB + _ch * 16; \
            } else {                                                              \
                int _t2 = _task - 512;                                            \
                int _mat = _t2 >> 9, _w = _t2 & 511;                              \
                int _row = _w >> 2, _ch = _w & 3;                                 \
                _g = (_mat ? base3 : base2) + (size_t)_row * K + _k0 + _ch * 8;   \
                _d = sb + (buf) * G_STGB + G_WOFF + _mat * 10240 + _row * SKRB + _ch * 16; \
            }                                                                     \
            cpasync16(_d, _g);                                                    \
        }                                                                         \
    } while (0)

        LOAD_STAGE(0, 0);
        cp_commit();

        for (int s = 0; s < nsteps; s++) {
            if (s + 1 < nsteps) {
                LOAD_STAGE(s + 1, (s + 1) & 1);
                cp_commit();
                cp_wait<1>();
            } else {
                cp_wait<0>();
            }
            __syncthreads();

            uint32_t stg = sb + (s & 1) * G_STGB;
#pragma unroll
            for (int ks = 0; ks < 2; ks++) {
                uint32_t aH[2][4], aL[2][4];
#pragma unroll
                for (int mt = 0; mt < 2; mt++) {
                    uint32_t ra = stg + (wm * 32 + mt * 16 + arow) * SKRB + ks * 32 + akb;
                    ldm4(aH[mt], ra);
                    ldm4(aL[mt], ra + G_AOFF);
                }
#pragma unroll
                for (int np = 0; np < 2; np++) {
                    uint32_t bh[4], bl[4];
                    uint32_t rb = stg + G_WOFF + (wn * 32 + np * 16 + brow) * SKRB + ks * 32 + bkb;
                    ldm4(bh, rb);
                    ldm4(bl, rb + 10240);
#pragma unroll
                    for (int mt = 0; mt < 2; mt++) {
                        mma16816(acc[mt][np * 2],     aH[mt], &bh[0]);
                        mma16816(acc[mt][np * 2],     aH[mt], &bl[0]);
                        mma16816(acc[mt][np * 2],     aL[mt], &bh[0]);
                        mma16816(acc[mt][np * 2 + 1], aH[mt], &bh[2]);
                        mma16816(acc[mt][np * 2 + 1], aH[mt], &bl[2]);
                        mma16816(acc[mt][np * 2 + 1], aL[mt], &bh[2]);
                    }
                }
            }
            __syncthreads();
        }

        // ---- epilogue ----
        const int rbase = m0 + wm * 32 + (lane >> 2);
        const int cbase = n0 + wn * 32 + (lane & 3) * 2;
#pragma unroll
        for (int mt = 0; mt < 2; mt++) {
#pragma unroll
            for (int nt = 0; nt < 4; nt++) {
                int col = cbase + nt * 8;
                float b0 = bias[col], b1 = bias[col + 1];
#pragma unroll
                for (int half = 0; half < 2; half++) {
                    int row = rbase + mt * 16 + half * 8;
                    float c0 = acc[mt][nt][half * 2 + 0] + b0;
                    float c1 = acc[mt][nt][half * 2 + 1] + b1;
                    size_t idx = (size_t)row * Nld + col;
                    if (mode == 0) {
                        float2 v; v.x = c0; v.y = c1;
                        *(float2*)&outF[idx] = v;
                    } else {
                        if (mode == 1) {
                            c0 = 0.5f * c0 * (1.0f + erff(c0 * 0.7071067811865475f));
                            c1 = 0.5f * c1 * (1.0f + erff(c1 * 0.7071067811865475f));
                        } else if (col < 256) {  // mode 2: pre-scale Q
                            c0 *= QSCALE;
                            c1 *= QSCALE;
                        }
                        __nv_bfloat16 h0 = __float2bfloat16(c0);
                        __nv_bfloat16 h1 = __float2bfloat16(c1);
                        __nv_bfloat162 hp; hp.x = h0; hp.y = h1;
                        __nv_bfloat162 lp;
                        lp.x = __float2bfloat16(c0 - __bfloat162float(h0));
                        lp.y = __float2bfloat16(c1 - __bfloat162float(h1));
                        *(__nv_bfloat162*)&outH[idx] = hp;
                        *(__nv_bfloat162*)&outL[idx] = lp;
                    }
                }
            }
        }
    }
}

// ================= persistent tensor-core flash attention =====================
// R12 inner body wrapped in a work-item loop (grid = min(512, 2*SMs)).
// Items ordered bh*8 + qtile so consecutive items share K/V (L2 reuse).
#define AK 80                 // K/V/Q smem row stride bytes
#define AQHo 0
#define AQLo 10240
#define ASTo 20480
#define ASTB 20480            // per stage: Kh 0, Kl 5120, Vh 10240, Vl 15360
#define AMo (ASTo + 2 * ASTB) // 61440: mask stages
#define AMSTRIDE 144          // 128B row + 16B pad (16B-aligned, conflict-free)
#define AMSTG (128 * AMSTRIDE) // 18432
#define ATT_SMEM (AMo + 2 * AMSTG) // 98304
#define AITEMS ((Rr / 128) * Bb * Hh) // 512

__global__ void __launch_bounds__(256, 2) mma_attn_kernel(
    const __nv_bfloat16* __restrict__ qh_g, const __nv_bfloat16* __restrict__ ql_g,
    const __nv_bfloat16* __restrict__ maskh,
    __nv_bfloat16* __restrict__ oh_g, __nv_bfloat16* __restrict__ ol_g) {
    extern __shared__ __align__(16) char smem[];
    uint32_t sb = smem_u32(smem);
    const int tid = threadIdx.x, lane = tid & 31, wid = tid >> 5;
    const int wq = wid * 16;

    const int arow = lane & 15;
    const int akb = (lane >> 4) * 16;
    const int brow = ((lane >> 4) & 1) * 8 + (lane & 7);
    const int bkb = ((lane >> 3) & 1) * 16;

#define LOADKV(kt, buf)                                                          \
    do {                                                                          \
        int _k0 = (kt) * 64;                                                      \
        _Pragma("unroll")                                                         \
        for (int _i = 0; _i < 4; _i++) {                                          \
            int _t = tid + _i * 256;                                              \
            int _mat = _t >> 8, _w = _t & 255, _row = _w >> 2, _ch = _w & 3;      \
            const __nv_bfloat16* _g = ((_mat & 1) ? ql_g : qh_g)                  \
                + ((size_t)(bI * Rr + _k0 + _row)) * 768                          \
                + ((_mat >> 1) ? 512 : 256) + h * 32 + _ch * 8;                   \
            cpasync16(sb + ASTo + (buf) * ASTB + _mat * 5120 + _row * AK + _ch * 16, _g); \
        }                                                                         \
    } while (0)
#define LOADMASK(kt, buf)                                                        \
    do {                                                                          \
        int _k0 = (kt) * 64;                                                      \
        _Pragma("unroll")                                                         \
        for (int _i = 0; _i < 4; _i++) {                                          \
            int _t = tid + _i * 256;                                              \
            int _row = _t >> 3, _ch = _t & 7;                                     \
            const __nv_bfloat16* _g = maskh                                       \
                + ((size_t)(bI * Rr + q0 + _row)) * Rr + _k0 + _ch * 8;           \
            cpasync16(sb + AMo + (buf) * AMSTG + _row * AMSTRIDE + _ch * 16, _g); \
        }                                                                         \
    } while (0)

    for (int item = blockIdx.x; item < AITEMS; item += gridDim.x) {
        const int bh = item >> 3;          // 0..63 (b*8 + h)
        const int bI = bh >> 3, h = bh & 7;
        const int q0 = (item & 7) * 128;

        // ---- prologue: Q tile + KV0 + MASK0 in one group
#pragma unroll
        for (int i = 0; i < 4; i++) {
            int task = tid + i * 256;
            int mat = task >> 9, w = task & 511, row = w >> 2, ch = w & 3;
            const __nv_bfloat16* g = (mat ? ql_g : qh_g)
                + ((size_t)(bI * Rr + q0 + row)) * 768 + h * 32 + ch * 8;
            cpasync16(sb + (mat ? AQLo : AQHo) + row * AK + ch * 16, g);
        }
        LOADKV(0, 0);
        LOADMASK(0, 0);
        cp_commit();

        uint32_t qfh[2][4], qfl[2][4];
        float oacc[4][4];
#pragma unroll
        for (int nt = 0; nt < 4; nt++)
#pragma unroll
            for (int j = 0; j < 4; j++) oacc[nt][j] = 0.0f;
        float mp0 = -1e30f, mp1 = -1e30f, l0 = 0.0f, l1 = 0.0f;

        for (int kt = 0; kt < 16; kt++) {
            if (kt + 1 < 16) {
                LOADKV(kt + 1, (kt + 1) & 1);
                LOADMASK(kt + 1, (kt + 1) & 1);
                cp_commit();
                cp_wait<1>();
            } else {
                cp_wait<0>();
            }
            __syncthreads();

            if (kt == 0) {
#pragma unroll
                for (int ks = 0; ks < 2; ks++) {
                    uint32_t ra = sb + AQHo + (wq + arow) * AK + ks * 32 + akb;
                    ldm4(qfh[ks], ra);
                    ldm4(qfl[ks], ra + 10240);
                }
            }

            uint32_t stg = sb + ASTo + (kt & 1) * ASTB;

            float s[8][4];
#pragma unroll
            for (int j = 0; j < 8; j++)
#pragma unroll
                for (int q = 0; q < 4; q++) s[j][q] = 0.0f;
#pragma unroll
            for (int ks = 0; ks < 2; ks++) {
#pragma unroll
                for (int np = 0; np < 4; np++) {
                    uint32_t kh[4], kl[4];
                    uint32_t rbadr = stg + (np * 16 + brow) * AK + ks * 32 + bkb;
                    ldm4(kh, rbadr);
                    ldm4(kl, rbadr + 5120);
                    mma16816(s[np * 2],     qfh[ks], &kh[0]);
                    mma16816(s[np * 2],     qfh[ks], &kl[0]);
                    mma16816(s[np * 2],     qfl[ks], &kh[0]);
                    mma16816(s[np * 2 + 1], qfh[ks], &kh[2]);
                    mma16816(s[np * 2 + 1], qfh[ks], &kl[2]);
                    mma16816(s[np * 2 + 1], qfl[ks], &kh[2]);
                }
            }

            const char* mbase = smem + AMo + (size_t)(kt & 1) * AMSTG
                + (wq + (lane >> 2)) * AMSTRIDE + (lane & 3) * 4;
            float mt0 = -1e30f, mt1 = -1e30f;
#pragma unroll
            for (int j = 0; j < 8; j++) {
                float2 a = __bfloat1622float2(*(const __nv_bfloat162*)(mbase + j * 16));
                float2 c = __bfloat1622float2(*(const __nv_bfloat162*)(mbase + 8 * AMSTRIDE + j * 16));
                s[j][0] += a.x; s[j][1] += a.y;
                s[j][2] += c.x; s[j][3] += c.y;
                mt0 = fmaxf(mt0, fmaxf(s[j][0], s[j][1]));
                mt1 = fmaxf(mt1, fmaxf(s[j][2], s[j][3]));
            }
            mt0 = fmaxf(mt0, __shfl_xor_sync(0xffffffffu, mt0, 1));
            mt0 = fmaxf(mt0, __shfl_xor_sync(0xffffffffu, mt0, 2));
            mt1 = fmaxf(mt1, __shfl_xor_sync(0xffffffffu, mt1, 1));
            mt1 = fmaxf(mt1, __shfl_xor_sync(0xffffffffu, mt1, 2));
            float mn0 = fmaxf(mp0, mt0), mn1 = fmaxf(mp1, mt1);
            float al0 = __expf(mp0 - mn0), al1 = __expf(mp1 - mn1);
            mp0 = mn0; mp1 = mn1;
            float ps0 = 0.0f, ps1 = 0.0f;
#pragma unroll
            for (int j = 0; j < 8; j++) {
                s[j][0] = __expf(s[j][0] - mn0);
                s[j][1] = __expf(s[j][1] - mn0);
                s[j][2] = __expf(s[j][2] - mn1);
                s[j][3] = __expf(s[j][3] - mn1);
                ps0 += s[j][0] + s[j][1];
                ps1 += s[j][2] + s[j][3];
            }
            ps0 += __shfl_xor_sync(0xffffffffu, ps0, 1);
            ps0 += __shfl_xor_sync(0xffffffffu, ps0, 2);
            ps1 += __shfl_xor_sync(0xffffffffu, ps1, 1);
            ps1 += __shfl_xor_sync(0xffffffffu, ps1, 2);
            l0 = l0 * al0 + ps0;
            l1 = l1 * al1 + ps1;
#pragma unroll
            for (int nt = 0; nt < 4; nt++) {
                oacc[nt][0] *= al0; oacc[nt][1] *= al0;
                oacc[nt][2] *= al1; oacc[nt][3] *= al1;
            }

#pragma unroll
            for (int ks2 = 0; ks2 < 4; ks2++) {
                int j0 = ks2 * 2, j1 = j0 + 1;
                uint32_t pah[4], pal[4];
                {
                    float r00 = s[j0][0], r01 = s[j0][1], r02 = s[j0][2], r03 = s[j0][3];
                    float r10 = s[j1][0], r11 = s[j1][1], r12 = s[j1][2], r13 = s[j1][3];
                    pah[0] = packbf(r00, r01);
                    pah[1] = packbf(r02, r03);
                    pah[2] = packbf(r10, r11);
                    pah[3] = packbf(r12, r13);
                    __nv_bfloat162 t;
                    t = reinterpret_cast<__nv_bfloat162&>(pah[0]);
                    pal[0] = packbf(r00 - __bfloat162float(t.x), r01 - __bfloat162float(t.y));
                    t = reinterpret_cast<__nv_bfloat162&>(pah[1]);
                    pal[1] = packbf(r02 - __bfloat162float(t.x), r03 - __bfloat162float(t.y));
                    t = reinterpret_cast<__nv_bfloat162&>(pah[2]);
                    pal[2] = packbf(r10 - __bfloat162float(t.x), r11 - __bfloat162float(t.y));
                    t = reinterpret_cast<__nv_bfloat162&>(pah[3]);
                    pal[3] = packbf(r12 - __bfloat162float(t.x), r13 - __bfloat162float(t.y));
                }
                uint32_t vrow = stg + 10240
                    + (ks2 * 16 + (lane & 7) + 8 * ((lane >> 3) & 1)) * AK
                    + ((lane >> 4) & 1) * 16;
#pragma unroll
                for (int nb = 0; nb < 2; nb++) {
                    uint32_t vh[4], vl[4];
                    ldm4t(vh, vrow + nb * 32);
                    ldm4t(vl, vrow + nb * 32 + 5120);
                    mma16816(oacc[nb * 2],     pah, &vh[0]);
                    mma16816(oacc[nb * 2],     pah, &vl[0]);
                    mma16816(oacc[nb * 2],     pal, &vh[0]);
                    mma16816(oacc[nb * 2 + 1], pah, &vh[2]);
                    mma16816(oacc[nb * 2 + 1], pah, &vl[2]);
                    mma16816(oacc[nb * 2 + 1], pal, &vh[2]);
                }
            }
            __syncthreads();
        }

        float i0 = 1.0f / l0, i1 = 1.0f / l1;
        size_t row0 = (size_t)(bI * Rr + q0 + wq + (lane >> 2));
#pragma unroll
        for (int nt = 0; nt < 4; nt++) {
            int col = h * 32 + nt * 8 + (lane & 3) * 2;
            float c0 = oacc[nt][0] * i0, c1 = oacc[nt][1] * i0;
            float c2 = oacc[nt][2] * i1, c3 = oacc[nt][3] * i1;
            size_t idx0 = row0 * Dm + col;
            size_t idx1 = (row0 + 8) * Dm + col;
            uint32_t h0 = packbf(c0, c1), h1 = packbf(c2, c3);
            __nv_bfloat162 t0 = reinterpret_cast<__nv_bfloat162&>(h0);
            __nv_bfloat162 t1 = reinterpret_cast<__nv_bfloat162&>(h1);
            *(uint32_t*)&oh_g[idx0] = h0;
            *(uint32_t*)&oh_g[idx1] = h1;
            *(uint32_t*)&ol_g[idx0] =
                packbf(c0 - __bfloat162float(t0.x), c1 - __bfloat162float(t0.y));
            *(uint32_t*)&ol_g[idx1] =
                packbf(c2 - __bfloat162float(t1.x), c3 - __bfloat162float(t1.y));
        }
        // trailing __syncthreads of kt=15 already fenced smem; epilogue used
        // registers only, so the next item's prologue may start immediately.
    }
}

// ================= fused residual-add + LayerNorm (warp per row) =============
__global__ void add_ln_kernel(float* __restrict__ x, const float* __restrict__ d,
                              const float* __restrict__ g, const float* __restrict__ bb,
                              __nv_bfloat16* __restrict__ xh, __nv_bfloat16* __restrict__ xl) {
    int wid = threadIdx.x >> 5, lane = threadIdx.x & 31;
    int row = blockIdx.x * 8 + wid;
    size_t base = (size_t)row * Dm;
    int c0 = lane * 4, c1 = lane * 4 + 128;

    float4 v0 = *(const float4*)&x[base + c0];
    float4 v1 = *(const float4*)&x[base + c1];
    float4 d0 = *(const float4*)&d[base + c0];
    float4 d1 = *(const float4*)&d[base + c1];
    v0.x += d0.x; v0.y += d0.y; v0.z += d0.z; v0.w += d0.w;
    v1.x += d1.x; v1.y += d1.y; v1.z += d1.z; v1.w += d1.w;

    float s = v0.x + v0.y + v0.z + v0.w + v1.x + v1.y + v1.z + v1.w;
#pragma unroll
    for (int off = 16; off > 0; off >>= 1) s += __shfl_xor_sync(0xffffffffu, s, off);
    float mu = s * (1.0f / Dm);

    float q = 0.0f;
    float e[8] = {v0.x - mu, v0.y - mu, v0.z - mu, v0.w - mu,
                  v1.x - mu, v1.y - mu, v1.z - mu, v1.w - mu};
#pragma unroll
    for (int j = 0; j < 8; j++) q += e[j] * e[j];
#pragma unroll
    for (int off = 16; off > 0; off >>= 1) q += __shfl_xor_sync(0xffffffffu, q, off);
    float rstd = rsqrtf(q * (1.0f / Dm) + 1e-5f);

    float4 g0 = *(const float4*)&g[c0];
    float4 g1 = *(const float4*)&g[c1];
    float4 b0 = *(const float4*)&bb[c0];
    float4 b1 = *(const float4*)&bb[c1];
    float y[8];
    y[0] = e[0] * rstd * g0.x + b0.x; y[1] = e[1] * rstd * g0.y + b0.y;
    y[2] = e[2] * rstd * g0.z + b0.z; y[3] = e[3] * rstd * g0.w + b0.w;
    y[4] = e[4] * rstd * g1.x + b1.x; y[5] = e[5] * rstd * g1.y + b1.y;
    y[6] = e[6] * rstd * g1.z + b1.z; y[7] = e[7] * rstd * g1.w + b1.w;

    float4 o0; o0.x = y[0]; o0.y = y[1]; o0.z = y[2]; o0.w = y[3];
    float4 o1; o1.x = y[4]; o1.y = y[5]; o1.z = y[6]; o1.w = y[7];
    *(float4*)&x[base + c0] = o0;
    *(float4*)&x[base + c1] = o1;

    uint32_t hp[4], lp[4];
#pragma unroll
    for (int j = 0; j < 4; j++) {
        float a = y[j * 2], b = y[j * 2 + 1];
        hp[j] = packbf(a, b);
        __nv_bfloat162 t = reinterpret_cast<__nv_bfloat162&>(hp[j]);
        lp[j] = packbf(a - __bfloat162float(t.x), b - __bfloat162float(t.y));
    }
    *(uint2*)&xh[base + c0] = make_uint2(hp[0], hp[1]);
    *(uint2*)&xh[base + c1] = make_uint2(hp[2], hp[3]);
    *(uint2*)&xl[base + c0] = make_uint2(lp[0], lp[1]);
    *(uint2*)&xl[base + c1] = make_uint2(lp[2], lp[3]);
}

// ================= launch =====================================================
extern "C" void kernel_launch(void* const* d_in, const int* in_sizes, int n_in,
                              void* d_out, int out_size) {
    const float* node = (const float*)d_in[0];
    const int* ei = (const int*)d_in[1];
    const int* rid = (const int*)d_in[2];
    const int* keep = (const int*)d_in[3];
    const float* rb = (const float*)d_in[4];
    const float* Wqkv = (const float*)d_in[5];
    const float* bqkv = (const float*)d_in[6];
    const float* Wo = (const float*)d_in[7];
    const float* bo = (const float*)d_in[8];
    const float* ln1g = (const float*)d_in[9];
    const float* ln1b = (const float*)d_in[10];
    const float* W1 = (const float*)d_in[11];
    const float* b1 = (const float*)d_in[12];
    const float* W2 = (const float*)d_in[13];
    const float* b2 = (const float*)d_in[14];
    const float* ln2g = (const float*)d_in[15];
    const float* ln2b = (const float*)d_in[16];
    float* x = (float*)d_out;

    float *mask, *tmp;
    __nv_bfloat16 *maskh, *qkvh, *qkvl, *xh, *xl, *ah, *al, *hh, *hl;
    __nv_bfloat16 *wqkvh, *wqkvl, *woh, *wol, *w1h, *w1l, *w2h, *w2l;
    cudaGetSymbolAddress((void**)&mask, g_mask);
    cudaGetSymbolAddress((void**)&maskh, g_maskh);
    cudaGetSymbolAddress((void**)&tmp, g_tmp);
    cudaGetSymbolAddress((void**)&qkvh, g_qkvh);
    cudaGetSymbolAddress((void**)&qkvl, g_qkvl);
    cudaGetSymbolAddress((void**)&xh, g_xh);
    cudaGetSymbolAddress((void**)&xl, g_xl);
    cudaGetSymbolAddress((void**)&ah, g_ah);
    cudaGetSymbolAddress((void**)&al, g_al);
    cudaGetSymbolAddress((void**)&hh, g_hh);
    cudaGetSymbolAddress((void**)&hl, g_hl);
    cudaGetSymbolAddress((void**)&wqkvh, g_wqkvh);
    cudaGetSymbolAddress((void**)&wqkvl, g_wqkvl);
    cudaGetSymbolAddress((void**)&woh, g_woh);
    cudaGetSymbolAddress((void**)&wol, g_wol);
    cudaGetSymbolAddress((void**)&w1h, g_w1h);
    cudaGetSymbolAddress((void**)&w1l, g_w1l);
    cudaGetSymbolAddress((void**)&w2h, g_w2h);
    cudaGetSymbolAddress((void**)&w2l, g_w2l);

    cudaFuncSetAttribute(mma_gemm_kernel, cudaFuncAttributeMaxDynamicSharedMemorySize, GEMM_SMEM);
    cudaFuncSetAttribute(mma_attn_kernel, cudaFuncAttributeMaxDynamicSharedMemorySize, ATT_SMEM);

    int nsm = 148;
    cudaDeviceGetAttribute(&nsm, cudaDevAttrMultiProcessorCount, 0);
    const int PGRID = 2 * nsm;
    const int AGRID = AITEMS < PGRID ? AITEMS : PGRID;

    const int mT = Mrows / 64;  // 128 m-tiles
#define LAUNCH_GEMM(Ahp, Alp, Whp, Wlp, biasp, outFp, outHp, outLp, Kv, Nv, modev)        \
    do {                                                                                   \
        int _nT = (Nv) / 128;                                                              \
        int _tot = _nT * mT;                                                               \
        int _grid = _tot < PGRID ? _tot : PGRID;                                           \
        mma_gemm_kernel<<<_grid, 256, GEMM_SMEM>>>(                                        \
            Ahp, Alp, Whp, Wlp, biasp, outFp, outHp, outLp, Kv, Nv, modev, _nT, _tot);     \
    } while (0)

    // Launch order: the ncu capture grabs launch #4 -> keep QKV GEMM there.
    copy_split_kernel<<<(Mrows * Dm + 255) / 256, 256>>>(node, x, xh, xl, Mrows * Dm);   // 1
    split_kernel<<<(Ll * 3 * Dm * Dm + 255) / 256, 256>>>(Wqkv, wqkvh, wqkvl,
                                                          Ll * 3 * Dm * Dm);             // 2
    mask_init_kernel<<<(Bb * Rr * Rr / 4 + 255) / 256, 256>>>(mask, maskh);              // 3
    // QKV projection (l=0) -> bf16 hi/lo, Q pre-scaled                                  // 4 <- ncu
    LAUNCH_GEMM(xh, xl, wqkvh, wqkvl, bqkv, nullptr, qkvh, qkvl, Dm, 3 * Dm, 2);
    mask_edges_zero_kernel<<<(Bb * Ee + 255) / 256, 256>>>(mask, maskh, ei, keep);       // 5
    mask_edges_bias_kernel<<<(Bb * Ee + 255) / 256, 256>>>(mask, ei, rid, keep, rb);     // 6
    mask_edges_fix_kernel<<<(Bb * Ee + 255) / 256, 256>>>(mask, maskh, ei, keep);        // 7

    bool w3_done = false;
    for (int l = 0; l < Ll; l++) {
        if (l > 0) {
            LAUNCH_GEMM(xh, xl, wqkvh + (size_t)l * 3 * Dm * Dm, wqkvl + (size_t)l * 3 * Dm * Dm,
                        bqkv + (size_t)l * 3 * Dm, nullptr, qkvh, qkvl, Dm, 3 * Dm, 2);
        }
        // persistent tensor-core flash attention -> att hi/lo
        mma_attn_kernel<<<AGRID, 256, ATT_SMEM>>>(qkvh, qkvl, maskh, ah, al);
        if (!w3_done) {
            split_w3_kernel<<<(NWO + NW1 + NW2 + 255) / 256, 256>>>(
                Wo, W1, W2, woh, wol, w1h, w1l, w2h, w2l);
            w3_done = true;
        }
        // Wo
        LAUNCH_GEMM(ah, al, woh + (size_t)l * Dm * Dm, wol + (size_t)l * Dm * Dm,
                    bo + (size_t)l * Dm, tmp, nullptr, nullptr, Dm, Dm, 0);
        add_ln_kernel<<<Mrows / 8, 256>>>(x, tmp, ln1g + (size_t)l * Dm, ln1b + (size_t)l * Dm, xh, xl);
        // FF1 + GELU -> h hi/lo
        LAUNCH_GEMM(xh, xl, w1h + (size_t)l * FFd * Dm, w1l + (size_t)l * FFd * Dm,
                    b1 + (size_t)l * FFd, nullptr, hh, hl, Dm, FFd, 1);
        // FF2
        LAUNCH_GEMM(hh, hl, w2h + (size_t)l * Dm * FFd, w2l + (size_t)l * Dm * FFd,
                    b2 + (size_t)l * Dm, tmp, nullptr, nullptr, FFd, Dm, 0);
        add_ln_kernel<<<Mrows / 8, 256>>>(x, tmp, ln2g + (size_t)l * Dm, ln2b + (size_t)l * Dm, xh, xl);
    }
}

// round 16
// speedup vs baseline: 1.5730x; 1.5730x over previous
#include <cuda_runtime.h>
#include <cuda_bf16.h>
#include <math.h>
#include <stdint.h>

#define Bb 8
#define Rr 1024
#define Dm 256
#define Hh 8
#define Ll 2
#define Ee 32768
#define FFd 1024
#define HDd 32
#define NEG -1000000000.0f

#define Mrows (Bb * Rr) // 8192
#define QSCALE 0.17677669529663687f

// ---------------- scratch (device globals; no allocation allowed) -----------
__device__ float g_mask[(size_t)Bb * Rr * Rr];          // 32 MB (fp32 build)
__device__ __nv_bfloat16 g_maskh[(size_t)Bb * Rr * Rr]; // 16 MB (attention copy)
__device__ float g_tmp [(size_t)Mrows * Dm];            // 8 MB
__device__ __nv_bfloat16 g_qkvh[(size_t)Mrows * 3 * Dm];
__device__ __nv_bfloat16 g_qkvl[(size_t)Mrows * 3 * Dm];
__device__ __nv_bfloat16 g_xh[(size_t)Mrows * Dm];
__device__ __nv_bfloat16 g_xl[(size_t)Mrows * Dm];
__device__ __nv_bfloat16 g_ah[(size_t)Mrows * Dm];
__device__ __nv_bfloat16 g_al[(size_t)Mrows * Dm];
__device__ __nv_bfloat16 g_hh[(size_t)Mrows * FFd];
__device__ __nv_bfloat16 g_hl[(size_t)Mrows * FFd];
__device__ __nv_bfloat16 g_wqkvh[(size_t)Ll * 3 * Dm * Dm];
__device__ __nv_bfloat16 g_wqkvl[(size_t)Ll * 3 * Dm * Dm];
__device__ __nv_bfloat16 g_woh[(size_t)Ll * Dm * Dm];
__device__ __nv_bfloat16 g_wol[(size_t)Ll * Dm * Dm];
__device__ __nv_bfloat16 g_w1h[(size_t)Ll * FFd * Dm];
__device__ __nv_bfloat16 g_w1l[(size_t)Ll * FFd * Dm];
__device__ __nv_bfloat16 g_w2h[(size_t)Ll * Dm * FFd];
__device__ __nv_bfloat16 g_w2l[(size_t)Ll * Dm * FFd];

// ---------------- PTX helpers (plain sm_80-class features only) --------------
__device__ __forceinline__ uint32_t smem_u32(const void* p) {
    uint32_t a;
    asm("{ .reg .u64 t; cvta.to.shared.u64 t, %1; cvt.u32.u64 %0, t; }" : "=r"(a) : "l"(p));
    return a;
}
__device__ __forceinline__ void cpasync16(uint32_t dst, const void* src) {
    asm volatile("cp.async.ca.shared.global [%0], [%1], 16;" :: "r"(dst), "l"(src) : "memory");
}
__device__ __forceinline__ void cp_commit() {
    asm volatile("cp.async.commit_group;" ::: "memory");
}
template <int N>
__device__ __forceinline__ void cp_wait() {
    asm volatile("cp.async.wait_group %0;" :: "n"(N) : "memory");
}
__device__ __forceinline__ void ldm4(uint32_t* r, uint32_t addr) {
    asm volatile("ldmatrix.sync.aligned.m8n8.x4.shared.b16 {%0,%1,%2,%3}, [%4];"
                 : "=r"(r[0]), "=r"(r[1]), "=r"(r[2]), "=r"(r[3]) : "r"(addr));
}
__device__ __forceinline__ void ldm4t(uint32_t* r, uint32_t addr) {
    asm volatile("ldmatrix.sync.aligned.m8n8.x4.trans.shared.b16 {%0,%1,%2,%3}, [%4];"
                 : "=r"(r[0]), "=r"(r[1]), "=r"(r[2]), "=r"(r[3]) : "r"(addr));
}
__device__ __forceinline__ void mma16816(float* c, const uint32_t* a, const uint32_t* b) {
    asm volatile(
        "mma.sync.aligned.m16n8k16.row.col.f32.bf16.bf16.f32 "
        "{%0,%1,%2,%3}, {%4,%5,%6,%7}, {%8,%9}, {%0,%1,%2,%3};"
        : "+f"(c[0]), "+f"(c[1]), "+f"(c[2]), "+f"(c[3])
        : "r"(a[0]), "r"(a[1]), "r"(a[2]), "r"(a[3]), "r"(b[0]), "r"(b[1]));
}
__device__ __forceinline__ uint32_t packbf(float x, float y) {
    __nv_bfloat162 t;
    t.x = __float2bfloat16(x);
    t.y = __float2bfloat16(y);
    return reinterpret_cast<uint32_t&>(t);
}

// ================= mask construction =========================================
__global__ void mask_init_kernel(float* __restrict__ m) {
    int i = blockIdx.x * blockDim.x + threadIdx.x;
    if (i >= Bb * Rr * Rr / 4) return;
    int rc = (i * 4) % (Rr * Rr);
    int row = rc / Rr, col = rc % Rr;
    float4 v;
    v.x = (col + 0 == row) ? 0.0f : NEG;
    v.y = (col + 1 == row) ? 0.0f : NEG;
    v.z = (col + 2 == row) ? 0.0f : NEG;
    v.w = (col + 3 == row) ? 0.0f : NEG;
    *(float4*)&m[(size_t)i * 4] = v;
}
__global__ void mask_edges_zero_kernel(float* __restrict__ m,
                                       const int* __restrict__ ei,
                                       const int* __restrict__ keep) {
    int idx = blockIdx.x * blockDim.x + threadIdx.x;
    if (idx >= Bb * Ee) return;
    if (!keep[idx]) return;
    int b = idx / Ee, e = idx % Ee;
    int src = ei[(size_t)b * 2 * Ee + e];
    int dst = ei[(size_t)b * 2 * Ee + Ee + e];
    m[((size_t)b * Rr + src) * Rr + dst] = 0.0f;
}
__global__ void mask_edges_bias_kernel(float* __restrict__ m,
                                       const int* __restrict__ ei,
                                       const int* __restrict__ rid,
                                       const int* __restrict__ keep,
                                       const float* __restrict__ rb) {
    int idx = blockIdx.x * blockDim.x + threadIdx.x;
    if (idx >= Bb * Ee) return;
    if (!keep[idx]) return;
    int b = idx / Ee, e = idx % Ee;
    int src = ei[(size_t)b * 2 * Ee + e];
    int dst = ei[(size_t)b * 2 * Ee + Ee + e];
    atomicAdd(&m[((size_t)b * Rr + src) * Rr + dst], rb[rid[idx]]);
}
// fp32 mask -> bf16 copy
__global__ void mask_cvt_kernel(const float* __restrict__ m,
                                __nv_bfloat16* __restrict__ mh) {
    int i = blockIdx.x * blockDim.x + threadIdx.x;
    if (i >= Bb * Rr * Rr / 4) return;
    float4 v = *(const float4*)&m[(size_t)i * 4];
    uint2 o;
    o.x = packbf(v.x, v.y);
    o.y = packbf(v.z, v.w);
    *(uint2*)&mh[(size_t)i * 4] = o;
}

// ================= fp32 -> bf16 hi/lo splits ==================================
__global__ void split_kernel(const float* __restrict__ src,
                             __nv_bfloat16* __restrict__ hi,
                             __nv_bfloat16* __restrict__ lo, int n) {
    int i = blockIdx.x * blockDim.x + threadIdx.x;
    if (i >= n) return;
    float v = src[i];
    __nv_bfloat16 h = __float2bfloat16(v);
    hi[i] = h;
    lo[i] = __float2bfloat16(v - __bfloat162float(h));
}
__global__ void copy_split_kernel(const float* __restrict__ src,
                                  float* __restrict__ dst,
                                  __nv_bfloat16* __restrict__ hi,
                                  __nv_bfloat16* __restrict__ lo, int n) {
    int i = blockIdx.x * blockDim.x + threadIdx.x;
    if (i >= n) return;
    float v = src[i];
    dst[i] = v;
    __nv_bfloat16 h = __float2bfloat16(v);
    hi[i] = h;
    lo[i] = __float2bfloat16(v - __bfloat162float(h));
}
#define NWO (Ll * Dm * Dm)
#define NW1 (Ll * FFd * Dm)
#define NW2 (Ll * Dm * FFd)
__global__ void split_w3_kernel(const float* __restrict__ Wo,
                                const float* __restrict__ W1,
                                const float* __restrict__ W2,
                                __nv_bfloat16* __restrict__ woh, __nv_bfloat16* __restrict__ wol,
                                __nv_bfloat16* __restrict__ w1h, __nv_bfloat16* __restrict__ w1l,
                                __nv_bfloat16* __restrict__ w2h, __nv_bfloat16* __restrict__ w2l) {
    int i = blockIdx.x * blockDim.x + threadIdx.x;
    const float* src;
    __nv_bfloat16 *hi, *lo;
    int j;
    if (i < NWO) { src = Wo; hi = woh; lo = wol; j = i; }
    else if (i < NWO + NW1) { src = W1; hi = w1h; lo = w1l; j = i - NWO; }
    else if (i < NWO + NW1 + NW2) { src = W2; hi = w2h; lo = w2l; j = i - NWO - NW1; }
    else return;
    float v = src[j];
    __nv_bfloat16 h = __float2bfloat16(v);
    hi[j] = h;
    lo[j] = __float2bfloat16(v - __bfloat162float(h));
}

// ================= split-bf16 HMMA GEMM (64x128 tile, occ 2) ==================
#define SKRB 80              // smem row stride bytes (40 bf16)
#define G_AOFF 5120          // Al offset within stage (Ah at 0)
#define G_WOFF 10240         // Wh offset within stage
#define G_STGB 30720         // stage bytes
#define GEMM_SMEM (2 * G_STGB) // 61440

__global__ void __launch_bounds__(256, 2) mma_gemm_kernel(
    const __nv_bfloat16* __restrict__ Ah, const __nv_bfloat16* __restrict__ Al,
    const __nv_bfloat16* __restrict__ Wh, const __nv_bfloat16* __restrict__ Wl,
    const float* __restrict__ bias,
    float* __restrict__ outF,
    __nv_bfloat16* __restrict__ outH, __nv_bfloat16* __restrict__ outL,
    int K, int Nld, int mode) {
    extern __shared__ __align__(16) char smem[];
    uint32_t sb = smem_u32(smem);
    const int tid = threadIdx.x, lane = tid & 31, wid = tid >> 5;
    const int wm = wid & 1, wn = wid >> 1;          // 2m x 4n warps
    const int m0 = blockIdx.y * 64, n0 = blockIdx.x * 128;

    const __nv_bfloat16* base0 = Ah + (size_t)m0 * K;
    const __nv_bfloat16* base1 = Al + (size_t)m0 * K;
    const __nv_bfloat16* base2 = Wh + (size_t)n0 * K;
    const __nv_bfloat16* base3 = Wl + (size_t)n0 * K;

    float acc[2][4][4];
#pragma unroll
    for (int mt = 0; mt < 2; mt++)
#pragma unroll
        for (int nt = 0; nt < 4; nt++)
#pragma unroll
            for (int j = 0; j < 4; j++) acc[mt][nt][j] = 0.0f;

    const int nsteps = K >> 5;

#define LOAD_STAGE(kstep, buf)                                                   \
    do {                                                                          \
        int _k0 = (kstep) * 32;                                                   \
        _Pragma("unroll")                                                         \
        for (int _i = 0; _i < 6; _i++) {                                          \
            int _task = tid + _i * 256;                                           \
            const __nv_bfloat16* _g;                                              \
            uint32_t _d;                                                          \
            if (_task < 512) {                                                    \
                int _mat = _task >> 8, _w = _task & 255;                          \
                int _row = _w >> 2, _ch = _w & 3;                                 \
                _g = (_mat ? base1 : base0) + (size_t)_row * K + _k0 + _ch * 8;   \
                _d = sb + (buf) * G_STGB + _mat * G_AOFF + _row * SKRB + _ch * 16; \
            } else {                                                              \
                int _t2 = _task - 512;                                            \
                int _mat = _t2 >> 9, _w = _t2 & 511;                              \
                int _row = _w >> 2, _ch = _w & 3;                                 \
                _g = (_mat ? base3 : base2) + (size_t)_row * K + _k0 + _ch * 8;   \
                _d = sb + (buf) * G_STGB + G_WOFF + _mat * 10240 + _row * SKRB + _ch * 16; \
            }                                                                     \
            cpasync16(_d, _g);                                                    \
        }                                                                         \
    } while (0)

    LOAD_STAGE(0, 0);
    cp_commit();

    const int arow = lane & 15;
    const int akb = (lane >> 4) * 16;
    const int brow = ((lane >> 4) & 1) * 8 + (lane & 7);
    const int bkb = ((lane >> 3) & 1) * 16;

    for (int s = 0; s < nsteps; s++) {
        if (s + 1 < nsteps) {
            LOAD_STAGE(s + 1, (s + 1) & 1);
            cp_commit();
            cp_wait<1>();
        } else {
            cp_wait<0>();
        }
        __syncthreads();

        uint32_t stg = sb + (s & 1) * G_STGB;
#pragma unroll
        for (int ks = 0; ks < 2; ks++) {
            uint32_t aH[2][4], aL[2][4];
#pragma unroll
            for (int mt = 0; mt < 2; mt++) {
                uint32_t ra = stg + (wm * 32 + mt * 16 + arow) * SKRB + ks * 32 + akb;
                ldm4(aH[mt], ra);
                ldm4(aL[mt], ra + G_AOFF);
            }
#pragma unroll
            for (int np = 0; np < 2; np++) {
                uint32_t bh[4], bl[4];
                uint32_t rb = stg + G_WOFF + (wn * 32 + np * 16 + brow) * SKRB + ks * 32 + bkb;
                ldm4(bh, rb);
                ldm4(bl, rb + 10240);
#pragma unroll
                for (int mt = 0; mt < 2; mt++) {
                    mma16816(acc[mt][np * 2],     aH[mt], &bh[0]);
                    mma16816(acc[mt][np * 2],     aH[mt], &bl[0]);
                    mma16816(acc[mt][np * 2],     aL[mt], &bh[0]);
                    mma16816(acc[mt][np * 2 + 1], aH[mt], &bh[2]);
                    mma16816(acc[mt][np * 2 + 1], aH[mt], &bl[2]);
                    mma16816(acc[mt][np * 2 + 1], aL[mt], &bh[2]);
                }
            }
        }
        __syncthreads();
    }

    // ---- epilogue ----
    const int rbase = m0 + wm * 32 + (lane >> 2);
    const int cbase = n0 + wn * 32 + (lane & 3) * 2;
#pragma unroll
    for (int mt = 0; mt < 2; mt++) {
#pragma unroll
        for (int nt = 0; nt < 4; nt++) {
            int col = cbase + nt * 8;
            float b0 = bias[col], b1 = bias[col + 1];
#pragma unroll
            for (int half = 0; half < 2; half++) {
                int row = rbase + mt * 16 + half * 8;
                float c0 = acc[mt][nt][half * 2 + 0] + b0;
                float c1 = acc[mt][nt][half * 2 + 1] + b1;
                size_t idx = (size_t)row * Nld + col;
                if (mode == 0) {
                    float2 v; v.x = c0; v.y = c1;
                    *(float2*)&outF[idx] = v;
                } else {
                    if (mode == 1) {
                        c0 = 0.5f * c0 * (1.0f + erff(c0 * 0.7071067811865475f));
                        c1 = 0.5f * c1 * (1.0f + erff(c1 * 0.7071067811865475f));
                    } else if (col < 256) {  // mode 2: pre-scale Q
                        c0 *= QSCALE;
                        c1 *= QSCALE;
                    }
                    __nv_bfloat16 h0 = __float2bfloat16(c0);
                    __nv_bfloat16 h1 = __float2bfloat16(c1);
                    __nv_bfloat162 hp; hp.x = h0; hp.y = h1;
                    __nv_bfloat162 lp;
                    lp.x = __float2bfloat16(c0 - __bfloat162float(h0));
                    lp.y = __float2bfloat16(c1 - __bfloat162float(h1));
                    *(__nv_bfloat162*)&outH[idx] = hp;
                    *(__nv_bfloat162*)&outL[idx] = lp;
                }
            }
        }
    }
}

// ================= tensor-core flash attention ===============================
// bf16 mask staged through smem via the cp.async pipeline (R12, best config).
#define AK 80                 // K/V/Q smem row stride bytes
#define AQHo 0
#define AQLo 10240
#define ASTo 20480
#define ASTB 20480            // per stage: Kh 0, Kl 5120, Vh 10240, Vl 15360
#define AMo (ASTo + 2 * ASTB) // 61440: mask stages
#define AMSTRIDE 144          // 128B row + 16B pad (16B-aligned, conflict-free)
#define AMSTG (128 * AMSTRIDE) // 18432
#define ATT_SMEM (AMo + 2 * AMSTG) // 98304

__global__ void __launch_bounds__(256, 2) mma_attn_kernel(
    const __nv_bfloat16* __restrict__ qh_g, const __nv_bfloat16* __restrict__ ql_g,
    const __nv_bfloat16* __restrict__ maskh,
    __nv_bfloat16* __restrict__ oh_g, __nv_bfloat16* __restrict__ ol_g) {
    extern __shared__ __align__(16) char smem[];
    uint32_t sb = smem_u32(smem);
    const int tid = threadIdx.x, lane = tid & 31, wid = tid >> 5;
    const int bI = blockIdx.y >> 3, h = blockIdx.y & 7;
    const int q0 = blockIdx.x * 128;
    const int wq = wid * 16;

#pragma unroll
    for (int i = 0; i < 4; i++) {
        int task = tid + i * 256;
        int mat = task >> 9, w = task & 511, row = w >> 2, ch = w & 3;
        const __nv_bfloat16* g = (mat ? ql_g : qh_g)
            + ((size_t)(bI * Rr + q0 + row)) * 768 + h * 32 + ch * 8;
        cpasync16(sb + (mat ? AQLo : AQHo) + row * AK + ch * 16, g);
    }
#define LOADKV(kt, buf)                                                          \
    do {                                                                          \
        int _k0 = (kt) * 64;                                                      \
        _Pragma("unroll")                                                         \
        for (int _i = 0; _i < 4; _i++) {                                          \
            int _t = tid + _i * 256;                                              \
            int _mat = _t >> 8, _w = _t & 255, _row = _w >> 2, _ch = _w & 3;      \
            const __nv_bfloat16* _g = ((_mat & 1) ? ql_g : qh_g)                  \
                + ((size_t)(bI * Rr + _k0 + _row)) * 768                          \
                + ((_mat >> 1) ? 512 : 256) + h * 32 + _ch * 8;                   \
            cpasync16(sb + ASTo + (buf) * ASTB + _mat * 5120 + _row * AK + _ch * 16, _g); \
        }                                                                         \
    } while (0)
#define LOADMASK(kt, buf)                                                        \
    do {                                                                          \
        int _k0 = (kt) * 64;                                                      \
        _Pragma("unroll")                                                         \
        for (int _i = 0; _i < 4; _i++) {                                          \
            int _t = tid + _i * 256;                                              \
            int _row = _t >> 3, _ch = _t & 7;                                     \
            const __nv_bfloat16* _g = maskh                                       \
                + ((size_t)(bI * Rr + q0 + _row)) * Rr + _k0 + _ch * 8;           \
            cpasync16(sb + AMo + (buf) * AMSTG + _row * AMSTRIDE + _ch * 16, _g); \
        }                                                                         \
    } while (0)

    LOADKV(0, 0);
    LOADMASK(0, 0);
    cp_commit();

    const int arow = lane & 15;
    const int akb = (lane >> 4) * 16;
    const int brow = ((lane >> 4) & 1) * 8 + (lane & 7);
    const int bkb = ((lane >> 3) & 1) * 16;

    uint32_t qfh[2][4], qfl[2][4];
    float oacc[4][4];
#pragma unroll
    for (int nt = 0; nt < 4; nt++)
#pragma unroll
        for (int j = 0; j < 4; j++) oacc[nt][j] = 0.0f;
    float mp0 = -1e30f, mp1 = -1e30f, l0 = 0.0f, l1 = 0.0f;

    for (int kt = 0; kt < 16; kt++) {
        if (kt + 1 < 16) {
            LOADKV(kt + 1, (kt + 1) & 1);
            LOADMASK(kt + 1, (kt + 1) & 1);
            cp_commit();
            cp_wait<1>();
        } else {
            cp_wait<0>();
        }
        __syncthreads();

        if (kt == 0) {
#pragma unroll
            for (int ks = 0; ks < 2; ks++) {
                uint32_t ra = sb + AQHo + (wq + arow) * AK + ks * 32 + akb;
                ldm4(qfh[ks], ra);
                ldm4(qfl[ks], ra + 10240);
            }
        }

        uint32_t stg = sb + ASTo + (kt & 1) * ASTB;

        float s[8][4];
#pragma unroll
        for (int j = 0; j < 8; j++)
#pragma unroll
            for (int q = 0; q < 4; q++) s[j][q] = 0.0f;
#pragma unroll
        for (int ks = 0; ks < 2; ks++) {
#pragma unroll
            for (int np = 0; np < 4; np++) {
                uint32_t kh[4], kl[4];
                uint32_t rbadr = stg + (np * 16 + brow) * AK + ks * 32 + bkb;
                ldm4(kh, rbadr);
                ldm4(kl, rbadr + 5120);
                mma16816(s[np * 2],     qfh[ks], &kh[0]);
                mma16816(s[np * 2],     qfh[ks], &kl[0]);
                mma16816(s[np * 2],     qfl[ks], &kh[0]);
                mma16816(s[np * 2 + 1], qfh[ks], &kh[2]);
                mma16816(s[np * 2 + 1], qfh[ks], &kl[2]);
                mma16816(s[np * 2 + 1], qfl[ks], &kh[2]);
            }
        }

        // ---- smem mask add + online softmax (rows r = lane>>2 and r+8)
        const char* mbase = smem + AMo + (size_t)(kt & 1) * AMSTG
            + (wq + (lane >> 2)) * AMSTRIDE + (lane & 3) * 4;
        float mt0 = -1e30f, mt1 = -1e30f;
#pragma unroll
        for (int j = 0; j < 8; j++) {
            float2 a = __bfloat1622float2(*(const __nv_bfloat162*)(mbase + j * 16));
            float2 c = __bfloat1622float2(*(const __nv_bfloat162*)(mbase + 8 * AMSTRIDE + j * 16));
            s[j][0] += a.x; s[j][1] += a.y;
            s[j][2] += c.x; s[j][3] += c.y;
            mt0 = fmaxf(mt0, fmaxf(s[j][0], s[j][1]));
            mt1 = fmaxf(mt1, fmaxf(s[j][2], s[j][3]));
        }
        mt0 = fmaxf(mt0, __shfl_xor_sync(0xffffffffu, mt0, 1));
        mt0 = fmaxf(mt0, __shfl_xor_sync(0xffffffffu, mt0, 2));
        mt1 = fmaxf(mt1, __shfl_xor_sync(0xffffffffu, mt1, 1));
        mt1 = fmaxf(mt1, __shfl_xor_sync(0xffffffffu, mt1, 2));
        float mn0 = fmaxf(mp0, mt0), mn1 = fmaxf(mp1, mt1);
        float al0 = __expf(mp0 - mn0), al1 = __expf(mp1 - mn1);
        mp0 = mn0; mp1 = mn1;
        float ps0 = 0.0f, ps1 = 0.0f;
#pragma unroll
        for (int j = 0; j < 8; j++) {
            s[j][0] = __expf(s[j][0] - mn0);
            s[j][1] = __expf(s[j][1] - mn0);
            s[j][2] = __expf(s[j][2] - mn1);
            s[j][3] = __expf(s[j][3] - mn1);
            ps0 += s[j][0] + s[j][1];
            ps1 += s[j][2] + s[j][3];
        }
        ps0 += __shfl_xor_sync(0xffffffffu, ps0, 1);
        ps0 += __shfl_xor_sync(0xffffffffu, ps0, 2);
        ps1 += __shfl_xor_sync(0xffffffffu, ps1, 1);
        ps1 += __shfl_xor_sync(0xffffffffu, ps1, 2);
        l0 = l0 * al0 + ps0;
        l1 = l1 * al1 + ps1;
#pragma unroll
        for (int nt = 0; nt < 4; nt++) {
            oacc[nt][0] *= al0; oacc[nt][1] *= al0;
            oacc[nt][2] *= al1; oacc[nt][3] *= al1;
        }

#pragma unroll
        for (int ks2 = 0; ks2 < 4; ks2++) {
            int j0 = ks2 * 2, j1 = j0 + 1;
            uint32_t pah[4], pal[4];
            {
                float r00 = s[j0][0], r01 = s[j0][1], r02 = s[j0][2], r03 = s[j0][3];
                float r10 = s[j1][0], r11 = s[j1][1], r12 = s[j1][2], r13 = s[j1][3];
                pah[0] = packbf(r00, r01);
                pah[1] = packbf(r02, r03);
                pah[2] = packbf(r10, r11);
                pah[3] = packbf(r12, r13);
                __nv_bfloat162 t;
                t = reinterpret_cast<__nv_bfloat162&>(pah[0]);
                pal[0] = packbf(r00 - __bfloat162float(t.x), r01 - __bfloat162float(t.y));
                t = reinterpret_cast<__nv_bfloat162&>(pah[1]);
                pal[1] = packbf(r02 - __bfloat162float(t.x), r03 - __bfloat162float(t.y));
                t = reinterpret_cast<__nv_bfloat162&>(pah[2]);
                pal[2] = packbf(r10 - __bfloat162float(t.x), r11 - __bfloat162float(t.y));
                t = reinterpret_cast<__nv_bfloat162&>(pah[3]);
                pal[3] = packbf(r12 - __bfloat162float(t.x), r13 - __bfloat162float(t.y));
            }
            uint32_t vrow = stg + 10240
                + (ks2 * 16 + (lane & 7) + 8 * ((lane >> 3) & 1)) * AK
                + ((lane >> 4) & 1) * 16;
#pragma unroll
            for (int nb = 0; nb < 2; nb++) {
                uint32_t vh[4], vl[4];
                ldm4t(vh, vrow + nb * 32);
                ldm4t(vl, vrow + nb * 32 + 5120);
                mma16816(oacc[nb * 2],     pah, &vh[0]);
                mma16816(oacc[nb * 2],     pah, &vl[0]);
                mma16816(oacc[nb * 2],     pal, &vh[0]);
                mma16816(oacc[nb * 2 + 1], pah, &vh[2]);
                mma16816(oacc[nb * 2 + 1], pah, &vl[2]);
                mma16816(oacc[nb * 2 + 1], pal, &vh[2]);
            }
        }
        __syncthreads();
    }

    float i0 = 1.0f / l0, i1 = 1.0f / l1;
    size_t row0 = (size_t)(bI * Rr + q0 + wq + (lane >> 2));
#pragma unroll
    for (int nt = 0; nt < 4; nt++) {
        int col = h * 32 + nt * 8 + (lane & 3) * 2;
        float c0 = oacc[nt][0] * i0, c1 = oacc[nt][1] * i0;
        float c2 = oacc[nt][2] * i1, c3 = oacc[nt][3] * i1;
        size_t idx0 = row0 * Dm + col;
        size_t idx1 = (row0 + 8) * Dm + col;
        uint32_t h0 = packbf(c0, c1), h1 = packbf(c2, c3);
        __nv_bfloat162 t0 = reinterpret_cast<__nv_bfloat162&>(h0);
        __nv_bfloat162 t1 = reinterpret_cast<__nv_bfloat162&>(h1);
        *(uint32_t*)&oh_g[idx0] = h0;
        *(uint32_t*)&oh_g[idx1] = h1;
        *(uint32_t*)&ol_g[idx0] =
            packbf(c0 - __bfloat162float(t0.x), c1 - __bfloat162float(t0.y));
        *(uint32_t*)&ol_g[idx1] =
            packbf(c2 - __bfloat162float(t1.x), c3 - __bfloat162float(t1.y));
    }
}

// ================= fused residual-add + LayerNorm (warp per row) =============
__global__ void add_ln_kernel(float* __restrict__ x, const float* __restrict__ d,
                              const float* __restrict__ g, const float* __restrict__ bb,
                              __nv_bfloat16* __restrict__ xh, __nv_bfloat16* __restrict__ xl) {
    int wid = threadIdx.x >> 5, lane = threadIdx.x & 31;
    int row = blockIdx.x * 8 + wid;
    size_t base = (size_t)row * Dm;
    int c0 = lane * 4, c1 = lane * 4 + 128;

    float4 v0 = *(const float4*)&x[base + c0];
    float4 v1 = *(const float4*)&x[base + c1];
    float4 d0 = *(const float4*)&d[base + c0];
    float4 d1 = *(const float4*)&d[base + c1];
    v0.x += d0.x; v0.y += d0.y; v0.z += d0.z; v0.w += d0.w;
    v1.x += d1.x; v1.y += d1.y; v1.z += d1.z; v1.w += d1.w;

    float s = v0.x + v0.y + v0.z + v0.w + v1.x + v1.y + v1.z + v1.w;
#pragma unroll
    for (int off = 16; off > 0; off >>= 1) s += __shfl_xor_sync(0xffffffffu, s, off);
    float mu = s * (1.0f / Dm);

    float q = 0.0f;
    float e[8] = {v0.x - mu, v0.y - mu, v0.z - mu, v0.w - mu,
                  v1.x - mu, v1.y - mu, v1.z - mu, v1.w - mu};
#pragma unroll
    for (int j = 0; j < 8; j++) q += e[j] * e[j];
#pragma unroll
    for (int off = 16; off > 0; off >>= 1) q += __shfl_xor_sync(0xffffffffu, q, off);
    float rstd = rsqrtf(q * (1.0f / Dm) + 1e-5f);

    float4 g0 = *(const float4*)&g[c0];
    float4 g1 = *(const float4*)&g[c1];
    float4 b0 = *(const float4*)&bb[c0];
    float4 b1 = *(const float4*)&bb[c1];
    float y[8];
    y[0] = e[0] * rstd * g0.x + b0.x; y[1] = e[1] * rstd * g0.y + b0.y;
    y[2] = e[2] * rstd * g0.z + b0.z; y[3] = e[3] * rstd * g0.w + b0.w;
    y[4] = e[4] * rstd * g1.x + b1.x; y[5] = e[5] * rstd * g1.y + b1.y;
    y[6] = e[6] * rstd * g1.z + b1.z; y[7] = e[7] * rstd * g1.w + b1.w;

    float4 o0; o0.x = y[0]; o0.y = y[1]; o0.z = y[2]; o0.w = y[3];
    float4 o1; o1.x = y[4]; o1.y = y[5]; o1.z = y[6]; o1.w = y[7];
    *(float4*)&x[base + c0] = o0;
    *(float4*)&x[base + c1] = o1;

    uint32_t hp[4], lp[4];
#pragma unroll
    for (int j = 0; j < 4; j++) {
        float a = y[j * 2], b = y[j * 2 + 1];
        hp[j] = packbf(a, b);
        __nv_bfloat162 t = reinterpret_cast<__nv_bfloat162&>(hp[j]);
        lp[j] = packbf(a - __bfloat162float(t.x), b - __bfloat162float(t.y));
    }
    *(uint2*)&xh[base + c0] = make_uint2(hp[0], hp[1]);
    *(uint2*)&xh[base + c1] = make_uint2(hp[2], hp[3]);
    *(uint2*)&xl[base + c0] = make_uint2(lp[0], lp[1]);
    *(uint2*)&xl[base + c1] = make_uint2(lp[2], lp[3]);
}

// ================= launch =====================================================
extern "C" void kernel_launch(void* const* d_in, const int* in_sizes, int n_in,
                              void* d_out, int out_size) {
    const float* node = (const float*)d_in[0];
    const int* ei = (const int*)d_in[1];
    const int* rid = (const int*)d_in[2];
    const int* keep = (const int*)d_in[3];
    const float* rb = (const float*)d_in[4];
    const float* Wqkv = (const float*)d_in[5];
    const float* bqkv = (const float*)d_in[6];
    const float* Wo = (const float*)d_in[7];
    const float* bo = (const float*)d_in[8];
    const float* ln1g = (const float*)d_in[9];
    const float* ln1b = (const float*)d_in[10];
    const float* W1 = (const float*)d_in[11];
    const float* b1 = (const float*)d_in[12];
    const float* W2 = (const float*)d_in[13];
    const float* b2 = (const float*)d_in[14];
    const float* ln2g = (const float*)d_in[15];
    const float* ln2b = (const float*)d_in[16];
    float* x = (float*)d_out;

    float *mask, *tmp;
    __nv_bfloat16 *maskh, *qkvh, *qkvl, *xh, *xl, *ah, *al, *hh, *hl;
    __nv_bfloat16 *wqkvh, *wqkvl, *woh, *wol, *w1h, *w1l, *w2h, *w2l;
    cudaGetSymbolAddress((void**)&mask, g_mask);
    cudaGetSymbolAddress((void**)&maskh, g_maskh);
    cudaGetSymbolAddress((void**)&tmp, g_tmp);
    cudaGetSymbolAddress((void**)&qkvh, g_qkvh);
    cudaGetSymbolAddress((void**)&qkvl, g_qkvl);
    cudaGetSymbolAddress((void**)&xh, g_xh);
    cudaGetSymbolAddress((void**)&xl, g_xl);
    cudaGetSymbolAddress((void**)&ah, g_ah);
    cudaGetSymbolAddress((void**)&al, g_al);
    cudaGetSymbolAddress((void**)&hh, g_hh);
    cudaGetSymbolAddress((void**)&hl, g_hl);
    cudaGetSymbolAddress((void**)&wqkvh, g_wqkvh);
    cudaGetSymbolAddress((void**)&wqkvl, g_wqkvl);
    cudaGetSymbolAddress((void**)&woh, g_woh);
    cudaGetSymbolAddress((void**)&wol, g_wol);
    cudaGetSymbolAddress((void**)&w1h, g_w1h);
    cudaGetSymbolAddress((void**)&w1l, g_w1l);
    cudaGetSymbolAddress((void**)&w2h, g_w2h);
    cudaGetSymbolAddress((void**)&w2l, g_w2l);

    cudaFuncSetAttribute(mma_gemm_kernel, cudaFuncAttributeMaxDynamicSharedMemorySize, GEMM_SMEM);
    cudaFuncSetAttribute(mma_attn_kernel, cudaFuncAttributeMaxDynamicSharedMemorySize, ATT_SMEM);

    // Launch order: the ncu capture grabs launch #4 -> keep QKV GEMM there.
    copy_split_kernel<<<(Mrows * Dm + 255) / 256, 256>>>(node, x, xh, xl, Mrows * Dm);   // 1
    split_kernel<<<(Ll * 3 * Dm * Dm + 255) / 256, 256>>>(Wqkv, wqkvh, wqkvl,
                                                          Ll * 3 * Dm * Dm);             // 2
    mask_init_kernel<<<(Bb * Rr * Rr / 4 + 255) / 256, 256>>>(mask);                     // 3
    // QKV projection (l=0) -> bf16 hi/lo, Q pre-scaled                                  // 4 <- ncu
    mma_gemm_kernel<<<dim3(3 * Dm / 128, Mrows / 64), 256, GEMM_SMEM>>>(
        xh, xl, wqkvh, wqkvl, bqkv, nullptr, qkvh, qkvl, Dm, 3 * Dm, 2);
    mask_edges_zero_kernel<<<(Bb * Ee + 255) / 256, 256>>>(mask, ei, keep);              // 5
    mask_edges_bias_kernel<<<(Bb * Ee + 255) / 256, 256>>>(mask, ei, rid, keep, rb);     // 6
    mask_cvt_kernel<<<(Bb * Rr * Rr / 4 + 255) / 256, 256>>>(mask, maskh);               // 7

    bool w3_done = false;
    for (int l = 0; l < Ll; l++) {
        if (l > 0) {
            mma_gemm_kernel<<<dim3(3 * Dm / 128, Mrows / 64), 256, GEMM_SMEM>>>(
                xh, xl, wqkvh + (size_t)l * 3 * Dm * Dm, wqkvl + (size_t)l * 3 * Dm * Dm,
                bqkv + (size_t)l * 3 * Dm, nullptr, qkvh, qkvl, Dm, 3 * Dm, 2);
        }
        // tensor-core flash attention -> att hi/lo
        mma_attn_kernel<<<dim3(Rr / 128, Bb * Hh), 256, ATT_SMEM>>>(qkvh, qkvl, maskh, ah, al);
        if (!w3_done) {
            split_w3_kernel<<<(NWO + NW1 + NW2 + 255) / 256, 256>>>(
                Wo, W1, W2, woh, wol, w1h, w1l, w2h, w2l);
            w3_done = true;
        }
        // Wo
        mma_gemm_kernel<<<dim3(Dm / 128, Mrows / 64), 256, GEMM_SMEM>>>(
            ah, al, woh + (size_t)l * Dm * Dm, wol + (size_t)l * Dm * Dm,
            bo + (size_t)l * Dm, tmp, nullptr, nullptr, Dm, Dm, 0);
        add_ln_kernel<<<Mrows / 8, 256>>>(x, tmp, ln1g + (size_t)l * Dm, ln1b + (size_t)l * Dm, xh, xl);
        // FF1 + GELU -> h hi/lo
        mma_gemm_kernel<<<dim3(FFd / 128, Mrows / 64), 256, GEMM_SMEM>>>(
            xh, xl, w1h + (size_t)l * FFd * Dm, w1l + (size_t)l * FFd * Dm,
            b1 + (size_t)l * FFd, nullptr, hh, hl, Dm, FFd, 1);
        // FF2
        mma_gemm_kernel<<<dim3(Dm / 128, Mrows / 64), 256, GEMM_SMEM>>>(
            hh, hl, w2h + (size_t)l * Dm * FFd, w2l + (size_t)l * Dm * FFd,
            b2 + (size_t)l * Dm, tmp, nullptr, nullptr, FFd, Dm, 0);
        add_ln_kernel<<<Mrows / 8, 256>>>(x, tmp, ln2g + (size_t)l * Dm, ln2b + (size_t)l * Dm, xh, xl);
    }
}

// round 17
// speedup vs baseline: 1.5985x; 1.0162x over previous
#include <cuda_runtime.h>
#include <cuda_bf16.h>
#include <math.h>
#include <stdint.h>

#define Bb 8
#define Rr 1024
#define Dm 256
#define Hh 8
#define Ll 2
#define Ee 32768
#define FFd 1024
#define HDd 32
#define NEG -1000000000.0f

#define Mrows (Bb * Rr) // 8192
#define QSCALE 0.17677669529663687f

// ---------------- scratch (device globals; no allocation allowed) -----------
__device__ float g_mask[(size_t)Bb * Rr * Rr];          // 32 MB (fp32 build)
__device__ __nv_bfloat16 g_maskh[(size_t)Bb * Rr * Rr]; // 16 MB (attention copy)
__device__ float g_tmp [(size_t)Mrows * Dm];            // 8 MB
__device__ __nv_bfloat16 g_qkvh[(size_t)Mrows * 3 * Dm];
__device__ __nv_bfloat16 g_qkvl[(size_t)Mrows * 3 * Dm];
__device__ __nv_bfloat16 g_xh[(size_t)Mrows * Dm];
__device__ __nv_bfloat16 g_xl[(size_t)Mrows * Dm];
__device__ __nv_bfloat16 g_ah[(size_t)Mrows * Dm];
__device__ __nv_bfloat16 g_al[(size_t)Mrows * Dm];
__device__ __nv_bfloat16 g_hh[(size_t)Mrows * FFd];
__device__ __nv_bfloat16 g_hl[(size_t)Mrows * FFd];
__device__ __nv_bfloat16 g_wqkvh[(size_t)Ll * 3 * Dm * Dm];
__device__ __nv_bfloat16 g_wqkvl[(size_t)Ll * 3 * Dm * Dm];
__device__ __nv_bfloat16 g_woh[(size_t)Ll * Dm * Dm];
__device__ __nv_bfloat16 g_wol[(size_t)Ll * Dm * Dm];
__device__ __nv_bfloat16 g_w1h[(size_t)Ll * FFd * Dm];
__device__ __nv_bfloat16 g_w1l[(size_t)Ll * FFd * Dm];
__device__ __nv_bfloat16 g_w2h[(size_t)Ll * Dm * FFd];
__device__ __nv_bfloat16 g_w2l[(size_t)Ll * Dm * FFd];

// ---------------- PTX helpers (plain sm_80-class features only) --------------
__device__ __forceinline__ uint32_t smem_u32(const void* p) {
    uint32_t a;
    asm("{ .reg .u64 t; cvta.to.shared.u64 t, %1; cvt.u32.u64 %0, t; }" : "=r"(a) : "l"(p));
    return a;
}
__device__ __forceinline__ void cpasync16(uint32_t dst, const void* src) {
    asm volatile("cp.async.ca.shared.global [%0], [%1], 16;" :: "r"(dst), "l"(src) : "memory");
}
__device__ __forceinline__ void cp_commit() {
    asm volatile("cp.async.commit_group;" ::: "memory");
}
template <int N>
__device__ __forceinline__ void cp_wait() {
    asm volatile("cp.async.wait_group %0;" :: "n"(N) : "memory");
}
__device__ __forceinline__ void ldm4(uint32_t* r, uint32_t addr) {
    asm volatile("ldmatrix.sync.aligned.m8n8.x4.shared.b16 {%0,%1,%2,%3}, [%4];"
                 : "=r"(r[0]), "=r"(r[1]), "=r"(r[2]), "=r"(r[3]) : "r"(addr));
}
__device__ __forceinline__ void ldm4t(uint32_t* r, uint32_t addr) {
    asm volatile("ldmatrix.sync.aligned.m8n8.x4.trans.shared.b16 {%0,%1,%2,%3}, [%4];"
                 : "=r"(r[0]), "=r"(r[1]), "=r"(r[2]), "=r"(r[3]) : "r"(addr));
}
__device__ __forceinline__ void mma16816(float* c, const uint32_t* a, const uint32_t* b) {
    asm volatile(
        "mma.sync.aligned.m16n8k16.row.col.f32.bf16.bf16.f32 "
        "{%0,%1,%2,%3}, {%4,%5,%6,%7}, {%8,%9}, {%0,%1,%2,%3};"
        : "+f"(c[0]), "+f"(c[1]), "+f"(c[2]), "+f"(c[3])
        : "r"(a[0]), "r"(a[1]), "r"(a[2]), "r"(a[3]), "r"(b[0]), "r"(b[1]));
}
__device__ __forceinline__ uint32_t packbf(float x, float y) {
    __nv_bfloat162 t;
    t.x = __float2bfloat16(x);
    t.y = __float2bfloat16(y);
    return reinterpret_cast<uint32_t&>(t);
}

// ================= mask construction =========================================
__global__ void mask_init_kernel(float* __restrict__ m) {
    int i = blockIdx.x * blockDim.x + threadIdx.x;
    if (i >= Bb * Rr * Rr / 4) return;
    int rc = (i * 4) % (Rr * Rr);
    int row = rc / Rr, col = rc % Rr;
    float4 v;
    v.x = (col + 0 == row) ? 0.0f : NEG;
    v.y = (col + 1 == row) ? 0.0f : NEG;
    v.z = (col + 2 == row) ? 0.0f : NEG;
    v.w = (col + 3 == row) ? 0.0f : NEG;
    *(float4*)&m[(size_t)i * 4] = v;
}
__global__ void mask_edges_zero_kernel(float* __restrict__ m,
                                       const int* __restrict__ ei,
                                       const int* __restrict__ keep) {
    int idx = blockIdx.x * blockDim.x + threadIdx.x;
    if (idx >= Bb * Ee) return;
    if (!keep[idx]) return;
    int b = idx / Ee, e = idx % Ee;
    int src = ei[(size_t)b * 2 * Ee + e];
    int dst = ei[(size_t)b * 2 * Ee + Ee + e];
    m[((size_t)b * Rr + src) * Rr + dst] = 0.0f;
}
__global__ void mask_edges_bias_kernel(float* __restrict__ m,
                                       const int* __restrict__ ei,
                                       const int* __restrict__ rid,
                                       const int* __restrict__ keep,
                                       const float* __restrict__ rb) {
    int idx = blockIdx.x * blockDim.x + threadIdx.x;
    if (idx >= Bb * Ee) return;
    if (!keep[idx]) return;
    int b = idx / Ee, e = idx % Ee;
    int src = ei[(size_t)b * 2 * Ee + e];
    int dst = ei[(size_t)b * 2 * Ee + Ee + e];
    atomicAdd(&m[((size_t)b * Rr + src) * Rr + dst], rb[rid[idx]]);
}
// fp32 mask -> bf16 copy
__global__ void mask_cvt_kernel(const float* __restrict__ m,
                                __nv_bfloat16* __restrict__ mh) {
    int i = blockIdx.x * blockDim.x + threadIdx.x;
    if (i >= Bb * Rr * Rr / 4) return;
    float4 v = *(const float4*)&m[(size_t)i * 4];
    uint2 o;
    o.x = packbf(v.x, v.y);
    o.y = packbf(v.z, v.w);
    *(uint2*)&mh[(size_t)i * 4] = o;
}

// ================= fp32 -> bf16 hi/lo splits ==================================
__global__ void split_kernel(const float* __restrict__ src,
                             __nv_bfloat16* __restrict__ hi,
                             __nv_bfloat16* __restrict__ lo, int n) {
    int i = blockIdx.x * blockDim.x + threadIdx.x;
    if (i >= n) return;
    float v = src[i];
    __nv_bfloat16 h = __float2bfloat16(v);
    hi[i] = h;
    lo[i] = __float2bfloat16(v - __bfloat162float(h));
}
__global__ void copy_split_kernel(const float* __restrict__ src,
                                  float* __restrict__ dst,
                                  __nv_bfloat16* __restrict__ hi,
                                  __nv_bfloat16* __restrict__ lo, int n) {
    int i = blockIdx.x * blockDim.x + threadIdx.x;
    if (i >= n) return;
    float v = src[i];
    dst[i] = v;
    __nv_bfloat16 h = __float2bfloat16(v);
    hi[i] = h;
    lo[i] = __float2bfloat16(v - __bfloat162float(h));
}
#define NWO (Ll * Dm * Dm)
#define NW1 (Ll * FFd * Dm)
#define NW2 (Ll * Dm * FFd)
__global__ void split_w3_kernel(const float* __restrict__ Wo,
                                const float* __restrict__ W1,
                                const float* __restrict__ W2,
                                __nv_bfloat16* __restrict__ woh, __nv_bfloat16* __restrict__ wol,
                                __nv_bfloat16* __restrict__ w1h, __nv_bfloat16* __restrict__ w1l,
                                __nv_bfloat16* __restrict__ w2h, __nv_bfloat16* __restrict__ w2l) {
    int i = blockIdx.x * blockDim.x + threadIdx.x;
    const float* src;
    __nv_bfloat16 *hi, *lo;
    int j;
    if (i < NWO) { src = Wo; hi = woh; lo = wol; j = i; }
    else if (i < NWO + NW1) { src = W1; hi = w1h; lo = w1l; j = i - NWO; }
    else if (i < NWO + NW1 + NW2) { src = W2; hi = w2h; lo = w2l; j = i - NWO - NW1; }
    else return;
    float v = src[j];
    __nv_bfloat16 h = __float2bfloat16(v);
    hi[j] = h;
    lo[j] = __float2bfloat16(v - __bfloat162float(h));
}

// ================= split-bf16 HMMA GEMM (64x128 tile, occ 2) ==================
#define SKRB 80              // smem row stride bytes (40 bf16)
#define G_AOFF 5120          // Al offset within stage (Ah at 0)
#define G_WOFF 10240         // Wh offset within stage
#define G_STGB 30720         // stage bytes
#define GEMM_SMEM (2 * G_STGB) // 61440

__global__ void __launch_bounds__(256, 2) mma_gemm_kernel(
    const __nv_bfloat16* __restrict__ Ah, const __nv_bfloat16* __restrict__ Al,
    const __nv_bfloat16* __restrict__ Wh, const __nv_bfloat16* __restrict__ Wl,
    const float* __restrict__ bias,
    float* __restrict__ outF,
    __nv_bfloat16* __restrict__ outH, __nv_bfloat16* __restrict__ outL,
    int K, int Nld, int mode) {
    extern __shared__ __align__(16) char smem[];
    uint32_t sb = smem_u32(smem);
    const int tid = threadIdx.x, lane = tid & 31, wid = tid >> 5;
    const int wm = wid & 1, wn = wid >> 1;          // 2m x 4n warps
    const int m0 = blockIdx.y * 64, n0 = blockIdx.x * 128;

    const __nv_bfloat16* base0 = Ah + (size_t)m0 * K;
    const __nv_bfloat16* base1 = Al + (size_t)m0 * K;
    const __nv_bfloat16* base2 = Wh + (size_t)n0 * K;
    const __nv_bfloat16* base3 = Wl + (size_t)n0 * K;

    float acc[2][4][4];
#pragma unroll
    for (int mt = 0; mt < 2; mt++)
#pragma unroll
        for (int nt = 0; nt < 4; nt++)
#pragma unroll
            for (int j = 0; j < 4; j++) acc[mt][nt][j] = 0.0f;

    const int nsteps = K >> 5;

#define LOAD_STAGE(kstep, buf)                                                   \
    do {                                                                          \
        int _k0 = (kstep) * 32;                                                   \
        _Pragma("unroll")                                                         \
        for (int _i = 0; _i < 6; _i++) {                                          \
            int _task = tid + _i * 256;                                           \
            const __nv_bfloat16* _g;                                              \
            uint32_t _d;                                                          \
            if (_task < 512) {                                                    \
                int _mat = _task >> 8, _w = _task & 255;                          \
                int _row = _w >> 2, _ch = _w & 3;                                 \
                _g = (_mat ? base1 : base0) + (size_t)_row * K + _k0 + _ch * 8;   \
                _d = sb + (buf) * G_STGB + _mat * G_AOFF + _row * SKRB + _ch * 16; \
            } else {                                                              \
                int _t2 = _task - 512;                                            \
                int _mat = _t2 >> 9, _w = _t2 & 511;                              \
                int _row = _w >> 2, _ch = _w & 3;                                 \
                _g = (_mat ? base3 : base2) + (size_t)_row * K + _k0 + _ch * 8;   \
                _d = sb + (buf) * G_STGB + G_WOFF + _mat * 10240 + _row * SKRB + _ch * 16; \
            }                                                                     \
            cpasync16(_d, _g);                                                    \
        }                                                                         \
    } while (0)

    LOAD_STAGE(0, 0);
    cp_commit();

    const int arow = lane & 15;
    const int akb = (lane >> 4) * 16;
    const int brow = ((lane >> 4) & 1) * 8 + (lane & 7);
    const int bkb = ((lane >> 3) & 1) * 16;

    for (int s = 0; s < nsteps; s++) {
        if (s + 1 < nsteps) {
            LOAD_STAGE(s + 1, (s + 1) & 1);
            cp_commit();
            cp_wait<1>();
        } else {
            cp_wait<0>();
        }
        __syncthreads();

        uint32_t stg = sb + (s & 1) * G_STGB;
#pragma unroll
        for (int ks = 0; ks < 2; ks++) {
            uint32_t aH[2][4], aL[2][4];
#pragma unroll
            for (int mt = 0; mt < 2; mt++) {
                uint32_t ra = stg + (wm * 32 + mt * 16 + arow) * SKRB + ks * 32 + akb;
                ldm4(aH[mt], ra);
                ldm4(aL[mt], ra + G_AOFF);
            }
#pragma unroll
            for (int np = 0; np < 2; np++) {
                uint32_t bh[4], bl[4];
                uint32_t rb = stg + G_WOFF + (wn * 32 + np * 16 + brow) * SKRB + ks * 32 + bkb;
                ldm4(bh, rb);
                ldm4(bl, rb + 10240);
#pragma unroll
                for (int mt = 0; mt < 2; mt++) {
                    mma16816(acc[mt][np * 2],     aH[mt], &bh[0]);
                    mma16816(acc[mt][np * 2],     aH[mt], &bl[0]);
                    mma16816(acc[mt][np * 2],     aL[mt], &bh[0]);
                    mma16816(acc[mt][np * 2 + 1], aH[mt], &bh[2]);
                    mma16816(acc[mt][np * 2 + 1], aH[mt], &bl[2]);
                    mma16816(acc[mt][np * 2 + 1], aL[mt], &bh[2]);
                }
            }
        }
        __syncthreads();
    }

    // ---- epilogue ----
    const int rbase = m0 + wm * 32 + (lane >> 2);
    const int cbase = n0 + wn * 32 + (lane & 3) * 2;
#pragma unroll
    for (int mt = 0; mt < 2; mt++) {
#pragma unroll
        for (int nt = 0; nt < 4; nt++) {
            int col = cbase + nt * 8;
            float b0 = bias[col], b1 = bias[col + 1];
#pragma unroll
            for (int half = 0; half < 2; half++) {
                int row = rbase + mt * 16 + half * 8;
                float c0 = acc[mt][nt][half * 2 + 0] + b0;
                float c1 = acc[mt][nt][half * 2 + 1] + b1;
                size_t idx = (size_t)row * Nld + col;
                if (mode == 0) {
                    float2 v; v.x = c0; v.y = c1;
                    *(float2*)&outF[idx] = v;
                } else {
                    if (mode == 1) {
                        c0 = 0.5f * c0 * (1.0f + erff(c0 * 0.7071067811865475f));
                        c1 = 0.5f * c1 * (1.0f + erff(c1 * 0.7071067811865475f));
                    } else if (col < 256) {  // mode 2: pre-scale Q
                        c0 *= QSCALE;
                        c1 *= QSCALE;
                    }
                    __nv_bfloat16 h0 = __float2bfloat16(c0);
                    __nv_bfloat16 h1 = __float2bfloat16(c1);
                    __nv_bfloat162 hp; hp.x = h0; hp.y = h1;
                    __nv_bfloat162 lp;
                    lp.x = __float2bfloat16(c0 - __bfloat162float(h0));
                    lp.y = __float2bfloat16(c1 - __bfloat162float(h1));
                    *(__nv_bfloat162*)&outH[idx] = hp;
                    *(__nv_bfloat162*)&outL[idx] = lp;
                }
            }
        }
    }
}

// ================= tensor-core flash attention ===============================
// bf16 mask staged through smem via the cp.async pipeline (R12/R16, best).
#define AK 80                 // K/V/Q smem row stride bytes
#define AQHo 0
#define AQLo 10240
#define ASTo 20480
#define ASTB 20480            // per stage: Kh 0, Kl 5120, Vh 10240, Vl 15360
#define AMo (ASTo + 2 * ASTB) // 61440: mask stages
#define AMSTRIDE 144          // 128B row + 16B pad (16B-aligned, conflict-free)
#define AMSTG (128 * AMSTRIDE) // 18432
#define ATT_SMEM (AMo + 2 * AMSTG) // 98304

__global__ void __launch_bounds__(256, 2) mma_attn_kernel(
    const __nv_bfloat16* __restrict__ qh_g, const __nv_bfloat16* __restrict__ ql_g,
    const __nv_bfloat16* __restrict__ maskh,
    __nv_bfloat16* __restrict__ oh_g, __nv_bfloat16* __restrict__ ol_g) {
    extern __shared__ __align__(16) char smem[];
    uint32_t sb = smem_u32(smem);
    const int tid = threadIdx.x, lane = tid & 31, wid = tid >> 5;
    const int bI = blockIdx.y >> 3, h = blockIdx.y & 7;
    const int q0 = blockIdx.x * 128;
    const int wq = wid * 16;

#pragma unroll
    for (int i = 0; i < 4; i++) {
        int task = tid + i * 256;
        int mat = task >> 9, w = task & 511, row = w >> 2, ch = w & 3;
        const __nv_bfloat16* g = (mat ? ql_g : qh_g)
            + ((size_t)(bI * Rr + q0 + row)) * 768 + h * 32 + ch * 8;
        cpasync16(sb + (mat ? AQLo : AQHo) + row * AK + ch * 16, g);
    }
#define LOADKV(kt, buf)                                                          \
    do {                                                                          \
        int _k0 = (kt) * 64;                                                      \
        _Pragma("unroll")                                                         \
        for (int _i = 0; _i < 4; _i++) {                                          \
            int _t = tid + _i * 256;                                              \
            int _mat = _t >> 8, _w = _t & 255, _row = _w >> 2, _ch = _w & 3;      \
            const __nv_bfloat16* _g = ((_mat & 1) ? ql_g : qh_g)                  \
                + ((size_t)(bI * Rr + _k0 + _row)) * 768                          \
                + ((_mat >> 1) ? 512 : 256) + h * 32 + _ch * 8;                   \
            cpasync16(sb + ASTo + (buf) * ASTB + _mat * 5120 + _row * AK + _ch * 16, _g); \
        }                                                                         \
    } while (0)
#define LOADMASK(kt, buf)                                                        \
    do {                                                                          \
        int _k0 = (kt) * 64;                                                      \
        _Pragma("unroll")                                                         \
        for (int _i = 0; _i < 4; _i++) {                                          \
            int _t = tid + _i * 256;                                              \
            int _row = _t >> 3, _ch = _t & 7;                                     \
            const __nv_bfloat16* _g = maskh                                       \
                + ((size_t)(bI * Rr + q0 + _row)) * Rr + _k0 + _ch * 8;           \
            cpasync16(sb + AMo + (buf) * AMSTG + _row * AMSTRIDE + _ch * 16, _g); \
        }                                                                         \
    } while (0)

    LOADKV(0, 0);
    LOADMASK(0, 0);
    cp_commit();

    const int arow = lane & 15;
    const int akb = (lane >> 4) * 16;
    const int brow = ((lane >> 4) & 1) * 8 + (lane & 7);
    const int bkb = ((lane >> 3) & 1) * 16;

    uint32_t qfh[2][4], qfl[2][4];
    float oacc[4][4];
#pragma unroll
    for (int nt = 0; nt < 4; nt++)
#pragma unroll
        for (int j = 0; j < 4; j++) oacc[nt][j] = 0.0f;
    float mp0 = -1e30f, mp1 = -1e30f, l0 = 0.0f, l1 = 0.0f;

    for (int kt = 0; kt < 16; kt++) {
        if (kt + 1 < 16) {
            LOADKV(kt + 1, (kt + 1) & 1);
            LOADMASK(kt + 1, (kt + 1) & 1);
            cp_commit();
            cp_wait<1>();
        } else {
            cp_wait<0>();
        }
        __syncthreads();

        if (kt == 0) {
#pragma unroll
            for (int ks = 0; ks < 2; ks++) {
                uint32_t ra = sb + AQHo + (wq + arow) * AK + ks * 32 + akb;
                ldm4(qfh[ks], ra);
                ldm4(qfl[ks], ra + 10240);
            }
        }

        uint32_t stg = sb + ASTo + (kt & 1) * ASTB;

        float s[8][4];
#pragma unroll
        for (int j = 0; j < 8; j++)
#pragma unroll
            for (int q = 0; q < 4; q++) s[j][q] = 0.0f;
#pragma unroll
        for (int ks = 0; ks < 2; ks++) {
#pragma unroll
            for (int np = 0; np < 4; np++) {
                uint32_t kh[4], kl[4];
                uint32_t rbadr = stg + (np * 16 + brow) * AK + ks * 32 + bkb;
                ldm4(kh, rbadr);
                ldm4(kl, rbadr + 5120);
                mma16816(s[np * 2],     qfh[ks], &kh[0]);
                mma16816(s[np * 2],     qfh[ks], &kl[0]);
                mma16816(s[np * 2],     qfl[ks], &kh[0]);
                mma16816(s[np * 2 + 1], qfh[ks], &kh[2]);
                mma16816(s[np * 2 + 1], qfh[ks], &kl[2]);
                mma16816(s[np * 2 + 1], qfl[ks], &kh[2]);
            }
        }

        // ---- smem mask add + online softmax (rows r = lane>>2 and r+8)
        const char* mbase = smem + AMo + (size_t)(kt & 1) * AMSTG
            + (wq + (lane >> 2)) * AMSTRIDE + (lane & 3) * 4;
        float mt0 = -1e30f, mt1 = -1e30f;
#pragma unroll
        for (int j = 0; j < 8; j++) {
            float2 a = __bfloat1622float2(*(const __nv_bfloat162*)(mbase + j * 16));
            float2 c = __bfloat1622float2(*(const __nv_bfloat162*)(mbase + 8 * AMSTRIDE + j * 16));
            s[j][0] += a.x; s[j][1] += a.y;
            s[j][2] += c.x; s[j][3] += c.y;
            mt0 = fmaxf(mt0, fmaxf(s[j][0], s[j][1]));
            mt1 = fmaxf(mt1, fmaxf(s[j][2], s[j][3]));
        }
        mt0 = fmaxf(mt0, __shfl_xor_sync(0xffffffffu, mt0, 1));
        mt0 = fmaxf(mt0, __shfl_xor_sync(0xffffffffu, mt0, 2));
        mt1 = fmaxf(mt1, __shfl_xor_sync(0xffffffffu, mt1, 1));
        mt1 = fmaxf(mt1, __shfl_xor_sync(0xffffffffu, mt1, 2));
        float mn0 = fmaxf(mp0, mt0), mn1 = fmaxf(mp1, mt1);
        float al0 = __expf(mp0 - mn0), al1 = __expf(mp1 - mn1);
        mp0 = mn0; mp1 = mn1;
        float ps0 = 0.0f, ps1 = 0.0f;
#pragma unroll
        for (int j = 0; j < 8; j++) {
            s[j][0] = __expf(s[j][0] - mn0);
            s[j][1] = __expf(s[j][1] - mn0);
            s[j][2] = __expf(s[j][2] - mn1);
            s[j][3] = __expf(s[j][3] - mn1);
            ps0 += s[j][0] + s[j][1];
            ps1 += s[j][2] + s[j][3];
        }
        ps0 += __shfl_xor_sync(0xffffffffu, ps0, 1);
        ps0 += __shfl_xor_sync(0xffffffffu, ps0, 2);
        ps1 += __shfl_xor_sync(0xffffffffu, ps1, 1);
        ps1 += __shfl_xor_sync(0xffffffffu, ps1, 2);
        l0 = l0 * al0 + ps0;
        l1 = l1 * al1 + ps1;
#pragma unroll
        for (int nt = 0; nt < 4; nt++) {
            oacc[nt][0] *= al0; oacc[nt][1] *= al0;
            oacc[nt][2] *= al1; oacc[nt][3] *= al1;
        }

#pragma unroll
        for (int ks2 = 0; ks2 < 4; ks2++) {
            int j0 = ks2 * 2, j1 = j0 + 1;
            uint32_t pah[4], pal[4];
            {
                float r00 = s[j0][0], r01 = s[j0][1], r02 = s[j0][2], r03 = s[j0][3];
                float r10 = s[j1][0], r11 = s[j1][1], r12 = s[j1][2], r13 = s[j1][3];
                pah[0] = packbf(r00, r01);
                pah[1] = packbf(r02, r03);
                pah[2] = packbf(r10, r11);
                pah[3] = packbf(r12, r13);
                __nv_bfloat162 t;
                t = reinterpret_cast<__nv_bfloat162&>(pah[0]);
                pal[0] = packbf(r00 - __bfloat162float(t.x), r01 - __bfloat162float(t.y));
                t = reinterpret_cast<__nv_bfloat162&>(pah[1]);
                pal[1] = packbf(r02 - __bfloat162float(t.x), r03 - __bfloat162float(t.y));
                t = reinterpret_cast<__nv_bfloat162&>(pah[2]);
                pal[2] = packbf(r10 - __bfloat162float(t.x), r11 - __bfloat162float(t.y));
                t = reinterpret_cast<__nv_bfloat162&>(pah[3]);
                pal[3] = packbf(r12 - __bfloat162float(t.x), r13 - __bfloat162float(t.y));
            }
            uint32_t vrow = stg + 10240
                + (ks2 * 16 + (lane & 7) + 8 * ((lane >> 3) & 1)) * AK
                + ((lane >> 4) & 1) * 16;
#pragma unroll
            for (int nb = 0; nb < 2; nb++) {
                uint32_t vh[4], vl[4];
                ldm4t(vh, vrow + nb * 32);
                ldm4t(vl, vrow + nb * 32 + 5120);
                mma16816(oacc[nb * 2],     pah, &vh[0]);
                mma16816(oacc[nb * 2],     pah, &vl[0]);
                mma16816(oacc[nb * 2],     pal, &vh[0]);
                mma16816(oacc[nb * 2 + 1], pah, &vh[2]);
                mma16816(oacc[nb * 2 + 1], pah, &vl[2]);
                mma16816(oacc[nb * 2 + 1], pal, &vh[2]);
            }
        }
        __syncthreads();
    }

    float i0 = 1.0f / l0, i1 = 1.0f / l1;
    size_t row0 = (size_t)(bI * Rr + q0 + wq + (lane >> 2));
#pragma unroll
    for (int nt = 0; nt < 4; nt++) {
        int col = h * 32 + nt * 8 + (lane & 3) * 2;
        float c0 = oacc[nt][0] * i0, c1 = oacc[nt][1] * i0;
        float c2 = oacc[nt][2] * i1, c3 = oacc[nt][3] * i1;
        size_t idx0 = row0 * Dm + col;
        size_t idx1 = (row0 + 8) * Dm + col;
        uint32_t h0 = packbf(c0, c1), h1 = packbf(c2, c3);
        __nv_bfloat162 t0 = reinterpret_cast<__nv_bfloat162&>(h0);
        __nv_bfloat162 t1 = reinterpret_cast<__nv_bfloat162&>(h1);
        *(uint32_t*)&oh_g[idx0] = h0;
        *(uint32_t*)&oh_g[idx1] = h1;
        *(uint32_t*)&ol_g[idx0] =
            packbf(c0 - __bfloat162float(t0.x), c1 - __bfloat162float(t0.y));
        *(uint32_t*)&ol_g[idx1] =
            packbf(c2 - __bfloat162float(t1.x), c3 - __bfloat162float(t1.y));
    }
}

// ================= fused residual-add + LayerNorm (warp per row) =============
__global__ void add_ln_kernel(float* __restrict__ x, const float* __restrict__ d,
                              const float* __restrict__ g, const float* __restrict__ bb,
                              __nv_bfloat16* __restrict__ xh, __nv_bfloat16* __restrict__ xl) {
    int wid = threadIdx.x >> 5, lane = threadIdx.x & 31;
    int row = blockIdx.x * 8 + wid;
    size_t base = (size_t)row * Dm;
    int c0 = lane * 4, c1 = lane * 4 + 128;

    float4 v0 = *(const float4*)&x[base + c0];
    float4 v1 = *(const float4*)&x[base + c1];
    float4 d0 = *(const float4*)&d[base + c0];
    float4 d1 = *(const float4*)&d[base + c1];
    v0.x += d0.x; v0.y += d0.y; v0.z += d0.z; v0.w += d0.w;
    v1.x += d1.x; v1.y += d1.y; v1.z += d1.z; v1.w += d1.w;

    float s = v0.x + v0.y + v0.z + v0.w + v1.x + v1.y + v1.z + v1.w;
#pragma unroll
    for (int off = 16; off > 0; off >>= 1) s += __shfl_xor_sync(0xffffffffu, s, off);
    float mu = s * (1.0f / Dm);

    float q = 0.0f;
    float e[8] = {v0.x - mu, v0.y - mu, v0.z - mu, v0.w - mu,
                  v1.x - mu, v1.y - mu, v1.z - mu, v1.w - mu};
#pragma unroll
    for (int j = 0; j < 8; j++) q += e[j] * e[j];
#pragma unroll
    for (int off = 16; off > 0; off >>= 1) q += __shfl_xor_sync(0xffffffffu, q, off);
    float rstd = rsqrtf(q * (1.0f / Dm) + 1e-5f);

    float4 g0 = *(const float4*)&g[c0];
    float4 g1 = *(const float4*)&g[c1];
    float4 b0 = *(const float4*)&bb[c0];
    float4 b1 = *(const float4*)&bb[c1];
    float y[8];
    y[0] = e[0] * rstd * g0.x + b0.x; y[1] = e[1] * rstd * g0.y + b0.y;
    y[2] = e[2] * rstd * g0.z + b0.z; y[3] = e[3] * rstd * g0.w + b0.w;
    y[4] = e[4] * rstd * g1.x + b1.x; y[5] = e[5] * rstd * g1.y + b1.y;
    y[6] = e[6] * rstd * g1.z + b1.z; y[7] = e[7] * rstd * g1.w + b1.w;

    float4 o0; o0.x = y[0]; o0.y = y[1]; o0.z = y[2]; o0.w = y[3];
    float4 o1; o1.x = y[4]; o1.y = y[5]; o1.z = y[6]; o1.w = y[7];
    *(float4*)&x[base + c0] = o0;
    *(float4*)&x[base + c1] = o1;

    uint32_t hp[4], lp[4];
#pragma unroll
    for (int j = 0; j < 4; j++) {
        float a = y[j * 2], b = y[j * 2 + 1];
        hp[j] = packbf(a, b);
        __nv_bfloat162 t = reinterpret_cast<__nv_bfloat162&>(hp[j]);
        lp[j] = packbf(a - __bfloat162float(t.x), b - __bfloat162float(t.y));
    }
    *(uint2*)&xh[base + c0] = make_uint2(hp[0], hp[1]);
    *(uint2*)&xh[base + c1] = make_uint2(hp[2], hp[3]);
    *(uint2*)&xl[base + c0] = make_uint2(lp[0], lp[1]);
    *(uint2*)&xl[base + c1] = make_uint2(lp[2], lp[3]);
}

// ================= launch =====================================================
extern "C" void kernel_launch(void* const* d_in, const int* in_sizes, int n_in,
                              void* d_out, int out_size) {
    const float* node = (const float*)d_in[0];
    const int* ei = (const int*)d_in[1];
    const int* rid = (const int*)d_in[2];
    const int* keep = (const int*)d_in[3];
    const float* rb = (const float*)d_in[4];
    const float* Wqkv = (const float*)d_in[5];
    const float* bqkv = (const float*)d_in[6];
    const float* Wo = (const float*)d_in[7];
    const float* bo = (const float*)d_in[8];
    const float* ln1g = (const float*)d_in[9];
    const float* ln1b = (const float*)d_in[10];
    const float* W1 = (const float*)d_in[11];
    const float* b1 = (const float*)d_in[12];
    const float* W2 = (const float*)d_in[13];
    const float* b2 = (const float*)d_in[14];
    const float* ln2g = (const float*)d_in[15];
    const float* ln2b = (const float*)d_in[16];
    float* x = (float*)d_out;

    float *mask, *tmp;
    __nv_bfloat16 *maskh, *qkvh, *qkvl, *xh, *xl, *ah, *al, *hh, *hl;
    __nv_bfloat16 *wqkvh, *wqkvl, *woh, *wol, *w1h, *w1l, *w2h, *w2l;
    cudaGetSymbolAddress((void**)&mask, g_mask);
    cudaGetSymbolAddress((void**)&maskh, g_maskh);
    cudaGetSymbolAddress((void**)&tmp, g_tmp);
    cudaGetSymbolAddress((void**)&qkvh, g_qkvh);
    cudaGetSymbolAddress((void**)&qkvl, g_qkvl);
    cudaGetSymbolAddress((void**)&xh, g_xh);
    cudaGetSymbolAddress((void**)&xl, g_xl);
    cudaGetSymbolAddress((void**)&ah, g_ah);
    cudaGetSymbolAddress((void**)&al, g_al);
    cudaGetSymbolAddress((void**)&hh, g_hh);
    cudaGetSymbolAddress((void**)&hl, g_hl);
    cudaGetSymbolAddress((void**)&wqkvh, g_wqkvh);
    cudaGetSymbolAddress((void**)&wqkvl, g_wqkvl);
    cudaGetSymbolAddress((void**)&woh, g_woh);
    cudaGetSymbolAddress((void**)&wol, g_wol);
    cudaGetSymbolAddress((void**)&w1h, g_w1h);
    cudaGetSymbolAddress((void**)&w1l, g_w1l);
    cudaGetSymbolAddress((void**)&w2h, g_w2h);
    cudaGetSymbolAddress((void**)&w2l, g_w2l);

    cudaFuncSetAttribute(mma_gemm_kernel, cudaFuncAttributeMaxDynamicSharedMemorySize, GEMM_SMEM);
    cudaFuncSetAttribute(mma_attn_kernel, cudaFuncAttributeMaxDynamicSharedMemorySize, ATT_SMEM);

    // ---- side stream for the independent preprocessing chain (fork-join). ----
    // Host-side handles only (no device memory); created once, reused per call
    // so every invocation records the identical work graph.
    static cudaStream_t s2 = nullptr;
    static cudaEvent_t evFork = nullptr, evJoin = nullptr;
    if (s2 == nullptr) {
        cudaStreamCreateWithFlags(&s2, cudaStreamNonBlocking);
        cudaEventCreateWithFlags(&evFork, cudaEventDisableTiming);
        cudaEventCreateWithFlags(&evJoin, cudaEventDisableTiming);
    }

    // Fork: chain B (mask build + Wo/W1/W2 splits) runs concurrently with
    // chain A (x/Wqkv splits + QKV GEMM). Join before attention needs maskh.
    cudaEventRecord(evFork, 0);
    cudaStreamWaitEvent(s2, evFork, 0);

    // chain B (stream s2)
    mask_init_kernel<<<(Bb * Rr * Rr / 4 + 255) / 256, 256, 0, s2>>>(mask);
    mask_edges_zero_kernel<<<(Bb * Ee + 255) / 256, 256, 0, s2>>>(mask, ei, keep);
    mask_edges_bias_kernel<<<(Bb * Ee + 255) / 256, 256, 0, s2>>>(mask, ei, rid, keep, rb);
    mask_cvt_kernel<<<(Bb * Rr * Rr / 4 + 255) / 256, 256, 0, s2>>>(mask, maskh);
    split_w3_kernel<<<(NWO + NW1 + NW2 + 255) / 256, 256, 0, s2>>>(
        Wo, W1, W2, woh, wol, w1h, w1l, w2h, w2l);
    cudaEventRecord(evJoin, s2);

    // chain A (default stream)
    copy_split_kernel<<<(Mrows * Dm + 255) / 256, 256>>>(node, x, xh, xl, Mrows * Dm);
    split_kernel<<<(Ll * 3 * Dm * Dm + 255) / 256, 256>>>(Wqkv, wqkvh, wqkvl,
                                                          Ll * 3 * Dm * Dm);
    mma_gemm_kernel<<<dim3(3 * Dm / 128, Mrows / 64), 256, GEMM_SMEM>>>(
        xh, xl, wqkvh, wqkvl, bqkv, nullptr, qkvh, qkvl, Dm, 3 * Dm, 2);

    // join: attention (and later Wo/FF GEMMs) need chain B's outputs
    cudaStreamWaitEvent(0, evJoin, 0);

    for (int l = 0; l < Ll; l++) {
        if (l > 0) {
            mma_gemm_kernel<<<dim3(3 * Dm / 128, Mrows / 64), 256, GEMM_SMEM>>>(
                xh, xl, wqkvh + (size_t)l * 3 * Dm * Dm, wqkvl + (size_t)l * 3 * Dm * Dm,
                bqkv + (size_t)l * 3 * Dm, nullptr, qkvh, qkvl, Dm, 3 * Dm, 2);
        }
        // tensor-core flash attention -> att hi/lo
        mma_attn_kernel<<<dim3(Rr / 128, Bb * Hh), 256, ATT_SMEM>>>(qkvh, qkvl, maskh, ah, al);
        // Wo
        mma_gemm_kernel<<<dim3(Dm / 128, Mrows / 64), 256, GEMM_SMEM>>>(
            ah, al, woh + (size_t)l * Dm * Dm, wol + (size_t)l * Dm * Dm,
            bo + (size_t)l * Dm, tmp, nullptr, nullptr, Dm, Dm, 0);
        add_ln_kernel<<<Mrows / 8, 256>>>(x, tmp, ln1g + (size_t)l * Dm, ln1b + (size_t)l * Dm, xh, xl);
        // FF1 + GELU -> h hi/lo
        mma_gemm_kernel<<<dim3(FFd / 128, Mrows / 64), 256, GEMM_SMEM>>>(
            xh, xl, w1h + (size_t)l * FFd * Dm, w1l + (size_t)l * FFd * Dm,
            b1 + (size_t)l * FFd, nullptr, hh, hl, Dm, FFd, 1);
        // FF2
        mma_gemm_kernel<<<dim3(Dm / 128, Mrows / 64), 256, GEMM_SMEM>>>(
            hh, hl, w2h + (size_t)l * Dm * FFd, w2l + (size_t)l * Dm * FFd,
            b2 + (size_t)l * Dm, tmp, nullptr, nullptr, FFd, Dm, 0);
        add_ln_kernel<<<Mrows / 8, 256>>>(x, tmp, ln2g + (size_t)l * Dm, ln2b + (size_t)l * Dm, xh, xl);
    }
}